// round 14
// baseline (speedup 1.0000x reference)
#include <cuda_runtime.h>
#include <cuda_fp16.h>
#include <cstdint>

#define BB 8
#define TT 1024
#define DD 1024
#define HH 16
#define DHX 64
#define MROWS (BB*TT)   // 8192

// fp16 scratch
__device__ __half g_xq[MROWS * DD];
__device__ __half g_xk[MROWS * DD];
__device__ __half g_xv[MROWS * DD];
__device__ __half g_wq[DD * DD];
__device__ __half g_wk[DD * DD];
__device__ __half g_wv[DD * DD];
__device__ __half g_wo[DD * DD];
__device__ __half g_qh[MROWS * DD];   // (B,H,T,DH)
__device__ __half g_kh[MROWS * DD];
__device__ __half g_vh[MROWS * DD];
__device__ __half g_ctxh[MROWS * DD]; // (B,T,D)
__device__ float  g_bias[BB * TT * TT]; // sp+ed, masked -> -1e30

// ---------------------------------------------------------------------------
// helpers
// ---------------------------------------------------------------------------
__device__ __forceinline__ unsigned packh2(float lo, float hi) {
    __half2 h = __floats2half2_rn(lo, hi);
    return *reinterpret_cast<unsigned*>(&h);
}
__device__ __forceinline__ uint32_t smem_u32(const void* p) {
    uint32_t a;
    asm("{ .reg .u64 t; cvta.to.shared.u64 t, %1; cvt.u32.u64 %0, t; }" : "=r"(a) : "l"(p));
    return a;
}
__device__ __forceinline__ void ldsm4(unsigned& r0, unsigned& r1, unsigned& r2, unsigned& r3,
                                      uint32_t addr) {
    asm volatile("ldmatrix.sync.aligned.m8n8.x4.shared.b16 {%0,%1,%2,%3}, [%4];"
                 : "=r"(r0), "=r"(r1), "=r"(r2), "=r"(r3) : "r"(addr));
}
__device__ __forceinline__ void ldsm4t(unsigned& r0, unsigned& r1, unsigned& r2, unsigned& r3,
                                       uint32_t addr) {
    asm volatile("ldmatrix.sync.aligned.m8n8.x4.trans.shared.b16 {%0,%1,%2,%3}, [%4];"
                 : "=r"(r0), "=r"(r1), "=r"(r2), "=r"(r3) : "r"(addr));
}
__device__ __forceinline__ void mma16(float& c0, float& c1, float& c2, float& c3,
                                      unsigned a0, unsigned a1, unsigned a2, unsigned a3,
                                      unsigned b0, unsigned b1) {
    asm("mma.sync.aligned.m16n8k16.row.col.f32.f16.f16.f32 "
        "{%0,%1,%2,%3}, {%4,%5,%6,%7}, {%8,%9}, {%0,%1,%2,%3};"
        : "+f"(c0), "+f"(c1), "+f"(c2), "+f"(c3)
        : "r"(a0), "r"(a1), "r"(a2), "r"(a3), "r"(b0), "r"(b1));
}
#define CP16(dst, src) \
    asm volatile("cp.async.cg.shared.global [%0], [%1], 16;" :: "r"(dst), "l"(src))
#define CP_COMMIT() asm volatile("cp.async.commit_group;" ::: "memory")
#define CP_WAIT1()  asm volatile("cp.async.wait_group 1;" ::: "memory")
#define PREF_L2(p)  asm volatile("prefetch.global.L2 [%0];" :: "l"(p))

// ---------------------------------------------------------------------------
// f32 -> fp16 conversion, z-batched
// ---------------------------------------------------------------------------
__global__ __launch_bounds__(256)
void to_half3(const float4* __restrict__ s0, const float4* __restrict__ s1,
              const float4* __restrict__ s2,
              uint2* __restrict__ d0, uint2* __restrict__ d1, uint2* __restrict__ d2)
{
    const float4* s = (blockIdx.z == 0) ? s0 : (blockIdx.z == 1) ? s1 : s2;
    uint2* d = (blockIdx.z == 0) ? d0 : (blockIdx.z == 1) ? d1 : d2;
    const int i = blockIdx.x * 256 + threadIdx.x;
    float4 v = s[i];
    d[i] = make_uint2(packh2(v.x, v.y), packh2(v.z, v.w));
}
__global__ __launch_bounds__(256)
void to_half4(const float4* __restrict__ s0, const float4* __restrict__ s1,
              const float4* __restrict__ s2, const float4* __restrict__ s3,
              uint2* __restrict__ d0, uint2* __restrict__ d1,
              uint2* __restrict__ d2, uint2* __restrict__ d3)
{
    const float4* s = (blockIdx.z == 0) ? s0 : (blockIdx.z == 1) ? s1 :
                      (blockIdx.z == 2) ? s2 : s3;
    uint2* d = (blockIdx.z == 0) ? d0 : (blockIdx.z == 1) ? d1 :
               (blockIdx.z == 2) ? d2 : d3;
    const int i = blockIdx.x * 256 + threadIdx.x;
    float4 v = s[i];
    d[i] = make_uint2(packh2(v.x, v.y), packh2(v.z, v.w));
}

// ---------------------------------------------------------------------------
// fp16 cp.async GEMM (unchanged from R13): C[8192,1024] = A @ W + bias
// MODE 0: z in {0,1,2} = QKV slices; z==3 = bias-fusion slice.
// MODE 1: f32 row-major out.
// ---------------------------------------------------------------------------
#define AP2 36
#define BP2 68
#define ASTG (128 * AP2)
#define BSTG (64 * BP2)
#define GSM  (3 * (ASTG + BSTG) * 4)   // 107520 bytes

template<int MODE>
__global__ __launch_bounds__(256, 2)
void gemm_ha(const __half* __restrict__ A0, const __half* __restrict__ A1, const __half* __restrict__ A2,
             const __half* __restrict__ W0, const __half* __restrict__ W1, const __half* __restrict__ W2,
             const float* __restrict__ bp0, const float* __restrict__ bp1, const float* __restrict__ bp2,
             void* __restrict__ O0, void* __restrict__ O1, void* __restrict__ O2,
             const float4* __restrict__ sp4, const float4* __restrict__ ed4,
             const unsigned* __restrict__ mask, float4* __restrict__ bias_out)
{
    const int tid = threadIdx.x;

    if (MODE == 0 && blockIdx.z == 3) {
        const int base_i = (blockIdx.y * 8 + blockIdx.x) * 256 + tid;
#pragma unroll
        for (int it = 0; it < 16; it++) {
            const int idx = base_i + it * 131072;
            const int b = idx >> 18;
            const int e4 = idx & 262143;
            const int col = (e4 & 255) << 2;
            const uint4 mk = *(const uint4*)&mask[b * TT + col];
            const float4 s = sp4[idx];
            const float4 e = ed4[idx];
            float4 o;
            o.x = mk.x ? -1e30f : (s.x + e.x);
            o.y = mk.y ? -1e30f : (s.y + e.y);
            o.z = mk.z ? -1e30f : (s.z + e.z);
            o.w = mk.w ? -1e30f : (s.w + e.w);
            bias_out[idx] = o;
        }
        return;
    }

    extern __shared__ __align__(16) unsigned smw[];
    const uint32_t base = smem_u32(smw);

    const int lane = tid & 31;
    const int warp = tid >> 5;
    const int g = lane >> 2;
    const int t = lane & 3;
    const int wm = warp >> 1;
    const int wn = warp & 1;
    const int m0 = blockIdx.y * 128;
    const int n0 = blockIdx.x * 128;

    const __half* A = A0; const __half* W = W0; const float* bias = bp0; void* out = O0;
    if (MODE == 0) {
        if (blockIdx.z == 1) { A = A1; W = W1; bias = bp1; out = O1; }
        else if (blockIdx.z == 2) { A = A2; W = W2; bias = bp2; out = O2; }
    }

    const int a_row = (lane & 7) + ((lane >> 3) & 1) * 8;
    const int a_kw  = (lane >> 4) * 4;
    const int b_krow = (lane & 7) + ((lane >> 3) & 1) * 8;
    const int b_j4   = (lane >> 4) * 4;

    auto aw = [&](int s) { return base + (uint32_t)(s * ASTG) * 4; };
    auto bw = [&](int s) { return base + (uint32_t)(3 * ASTG + s * BSTG) * 4; };

    auto issue_stage = [&](int kt, int s) {
        const int k0 = kt * 64;
        const uint32_t ab = aw(s), bb = bw(s);
#pragma unroll
        for (int it = 0; it < 4; it++) {
            int idx = tid + it * 256;
            int m = idx >> 3, ch = idx & 7;
            CP16(ab + (uint32_t)(m * AP2 + ch * 4) * 4,
                 &A[(size_t)(m0 + m) * DD + k0 + ch * 8]);
        }
#pragma unroll
        for (int it = 0; it < 4; it++) {
            int idx = tid + it * 256;
            int kk = idx >> 4, c = idx & 15;
            CP16(bb + (uint32_t)(kk * BP2 + c * 4) * 4,
                 &W[(size_t)(k0 + kk) * DD + n0 + c * 8]);
        }
    };

    issue_stage(0, 0); CP_COMMIT();
    issue_stage(1, 1); CP_COMMIT();

    float acc[2][8][4];
#pragma unroll
    for (int i = 0; i < 2; i++)
#pragma unroll
        for (int j = 0; j < 8; j++)
#pragma unroll
            for (int c = 0; c < 4; c++) acc[i][j][c] = 0.0f;

    for (int kt = 0; kt < 16; kt++) {
        CP_WAIT1();
        __syncthreads();
        if (kt + 2 < 16) issue_stage(kt + 2, (kt + 2) % 3);
        CP_COMMIT();

        const int s = kt % 3;
        const uint32_t as = aw(s), bs = bw(s);

#pragma unroll
        for (int ks = 0; ks < 4; ks++) {
            unsigned af[2][4];
#pragma unroll
            for (int i = 0; i < 2; i++)
                ldsm4(af[i][0], af[i][1], af[i][2], af[i][3],
                      as + (uint32_t)(((wm * 32 + i * 16 + a_row) * AP2) + ks * 8 + a_kw) * 4);
            unsigned bf[8][2];
#pragma unroll
            for (int jp = 0; jp < 4; jp++)
                ldsm4t(bf[2 * jp][0], bf[2 * jp][1], bf[2 * jp + 1][0], bf[2 * jp + 1][1],
                       bs + (uint32_t)(((ks * 16 + b_krow) * BP2) + wn * 32 + jp * 8 + b_j4) * 4);
#pragma unroll
            for (int i = 0; i < 2; i++)
#pragma unroll
                for (int j = 0; j < 8; j++)
                    mma16(acc[i][j][0], acc[i][j][1], acc[i][j][2], acc[i][j][3],
                          af[i][0], af[i][1], af[i][2], af[i][3],
                          bf[j][0], bf[j][1]);
        }
    }

#pragma unroll
    for (int i = 0; i < 2; i++) {
#pragma unroll
        for (int j = 0; j < 8; j++) {
            const int n = n0 + wn * 64 + j * 8 + t * 2;
            const float2 bb = *(const float2*)&bias[n];
#pragma unroll
            for (int h2 = 0; h2 < 2; h2++) {
                const int m = m0 + wm * 32 + i * 16 + g + h2 * 8;
                float vx = acc[i][j][h2 * 2 + 0] + bb.x;
                float vy = acc[i][j][h2 * 2 + 1] + bb.y;
                if (MODE == 0) {
                    int bidx = m >> 10, tt = m & 1023;
                    int hh = n >> 6, d = n & 63;
                    __half2 hv = __floats2half2_rn(vx, vy);
                    *(__half2*)&((__half*)out)[(((size_t)(bidx * HH + hh) << 10) + tt) * DHX + d] = hv;
                } else {
                    *(float2*)&((float*)out)[(size_t)m * DD + n] = make_float2(vx, vy);
                }
            }
        }
    }
}

// ---------------------------------------------------------------------------
// Fused flash attention v7: 64-row q-tile, 4 warps x 16 q-rows.
// Register state halved vs R13 (mt dimension removed) -> target 3 CTAs/SM
// (12 warps) enforced by __launch_bounds__(128, 3). Math identical to R13.
// smem: Q 64x36w + 3 stages x [K 64x36w | V 64x36w] = 64512 B.
// ---------------------------------------------------------------------------
#define QP2 36
#define QW  (64 * QP2)
#define KVW (64 * QP2)
#define ASMEM ((QW + 3 * 2 * KVW) * 4)   // 64512 bytes

__global__ __launch_bounds__(128, 3)
void attn_h(const float* __restrict__ gb)
{
    extern __shared__ __align__(16) unsigned smw[];
    const uint32_t base = smem_u32(smw);
    unsigned* Q2 = smw;

    const int tid  = threadIdx.x;
    const int lane = tid & 31;
    const int warp = tid >> 5;
    const int g = lane >> 2;
    const int t = lane & 3;
    const int q0 = blockIdx.x * 64;
    const int h  = blockIdx.y;
    const int b  = blockIdx.z;
    const int qb = warp * 16;

    const __half* Qg = g_qh + (size_t)(b * HH + h) * TT * DHX;
    const __half* Kg = g_kh + (size_t)(b * HH + h) * TT * DHX;
    const __half* Vg = g_vh + (size_t)(b * HH + h) * TT * DHX;
    // prefetch lane: threads 0-63 cover rows (first 32 floats), 64-127 second half
    const float* gbpref = &gb[((size_t)b * TT + q0 + (tid & 63)) * TT + (tid >> 6) * 32];

    const uint32_t sQ = base;
    auto sK = [&](int s) { return base + (uint32_t)(QW + s * 2 * KVW) * 4; };
    auto sV = [&](int s) { return base + (uint32_t)(QW + s * 2 * KVW + KVW) * 4; };

    const int a_row = (lane & 7) + ((lane >> 3) & 1) * 8;
    const int a_kw  = (lane >> 4) * 4;
    const int k_row = (lane & 7) + ((lane >> 4) & 1) * 8;
    const int k_kw  = ((lane >> 3) & 1) * 4;
    const int v_krow = (lane & 7) + ((lane >> 3) & 1) * 8;
    const int v_jw   = (lane >> 4) * 4;

    auto issue_kv = [&](int kt, int s) {
        const int k0 = kt * 64;
        const uint32_t kb = sK(s), vb = sV(s);
#pragma unroll
        for (int it = 0; it < 4; it++) {
            int idx = tid + it * 128;
            int r = idx >> 3, c = idx & 7;
            CP16(kb + (uint32_t)(r * QP2 + c * 4) * 4, &Kg[(size_t)(k0 + r) * DHX + c * 8]);
            CP16(vb + (uint32_t)(r * QP2 + c * 4) * 4, &Vg[(size_t)(k0 + r) * DHX + c * 8]);
        }
    };

    // Q tile (64 x 64 fp16)
#pragma unroll
    for (int it = 0; it < 4; it++) {
        int idx = tid + it * 128;
        int r = idx >> 3, u = idx & 7;
        uint4 qv = *(const uint4*)&Qg[(size_t)(q0 + r) * DHX + u * 8];
        *(uint4*)&Q2[r * QP2 + u * 4] = qv;
    }
    PREF_L2(gbpref);
    issue_kv(0, 0); CP_COMMIT();
    issue_kv(1, 1); CP_COMMIT();
    __syncthreads();

    unsigned qf[4][4];
#pragma unroll
    for (int ks = 0; ks < 4; ks++)
        ldsm4(qf[ks][0], qf[ks][1], qf[ks][2], qf[ks][3],
              sQ + (uint32_t)(((qb + a_row) * QP2) + ks * 8 + a_kw) * 4);

    float o[8][4];
#pragma unroll
    for (int j = 0; j < 8; j++)
#pragma unroll
        for (int c = 0; c < 4; c++) o[j][c] = 0.0f;
    float m_run[2] = {-3e38f, -3e38f};
    float l_run[2] = {0.0f, 0.0f};

    for (int kt = 0; kt < 16; kt++) {
        const int k0 = kt * 64;
        CP_WAIT1();
        __syncthreads();
        if (kt + 2 < 16) issue_kv(kt + 2, (kt + 2) % 3);
        CP_COMMIT();

        if (kt + 1 < 16) PREF_L2(gbpref + (kt + 1) * 64);

        const int s = kt % 3;
        const uint32_t kbs = sK(s), vbs = sV(s);

        // S = Q K^T
        float sc[8][4];
#pragma unroll
        for (int j = 0; j < 8; j++)
#pragma unroll
            for (int c = 0; c < 4; c++) sc[j][c] = 0.0f;

#pragma unroll
        for (int ks = 0; ks < 4; ks++) {
            unsigned kb[8][2];
#pragma unroll
            for (int jp = 0; jp < 4; jp++)
                ldsm4(kb[2 * jp][0], kb[2 * jp][1], kb[2 * jp + 1][0], kb[2 * jp + 1][1],
                      kbs + (uint32_t)(((jp * 16 + k_row) * QP2) + ks * 8 + k_kw) * 4);
#pragma unroll
            for (int j = 0; j < 8; j++)
                mma16(sc[j][0], sc[j][1], sc[j][2], sc[j][3],
                      qf[ks][0], qf[ks][1], qf[ks][2], qf[ks][3],
                      kb[j][0], kb[j][1]);
        }

        // scale + fused bias
#pragma unroll
        for (int j = 0; j < 8; j++) {
            const int col = k0 + j * 8 + t * 2;
            const size_t i0 = ((size_t)b * TT + (q0 + qb + g)) * TT + col;
            float2 b0 = *(const float2*)&gb[i0];
            float2 b1 = *(const float2*)&gb[i0 + (size_t)8 * TT];
            sc[j][0] = sc[j][0] * 0.125f + b0.x;
            sc[j][1] = sc[j][1] * 0.125f + b0.y;
            sc[j][2] = sc[j][2] * 0.125f + b1.x;
            sc[j][3] = sc[j][3] * 0.125f + b1.y;
        }

        // online softmax
#pragma unroll
        for (int r = 0; r < 2; r++) {
            float mx = -3e38f;
#pragma unroll
            for (int j = 0; j < 8; j++)
                mx = fmaxf(mx, fmaxf(sc[j][2 * r], sc[j][2 * r + 1]));
            mx = fmaxf(mx, __shfl_xor_sync(0xffffffffu, mx, 1));
            mx = fmaxf(mx, __shfl_xor_sync(0xffffffffu, mx, 2));
            float m_new = fmaxf(m_run[r], mx);
            float alpha = __expf(m_run[r] - m_new);
            m_run[r] = m_new;
            float ls = 0.0f;
#pragma unroll
            for (int j = 0; j < 8; j++) {
                float p0 = __expf(sc[j][2 * r] - m_new);
                float p1 = __expf(sc[j][2 * r + 1] - m_new);
                sc[j][2 * r] = p0; sc[j][2 * r + 1] = p1;
                ls += p0 + p1;
            }
            ls += __shfl_xor_sync(0xffffffffu, ls, 1);
            ls += __shfl_xor_sync(0xffffffffu, ls, 2);
            l_run[r] = l_run[r] * alpha + ls;
#pragma unroll
            for (int j = 0; j < 8; j++) {
                o[j][2 * r] *= alpha;
                o[j][2 * r + 1] *= alpha;
            }
        }

        // pack P into A fragments in registers
        unsigned pf[4][4];
#pragma unroll
        for (int c = 0; c < 4; c++) {
            pf[c][0] = packh2(sc[2 * c][0], sc[2 * c][1]);
            pf[c][1] = packh2(sc[2 * c][2], sc[2 * c][3]);
            pf[c][2] = packh2(sc[2 * c + 1][0], sc[2 * c + 1][1]);
            pf[c][3] = packh2(sc[2 * c + 1][2], sc[2 * c + 1][3]);
        }

        // O += P @ V
#pragma unroll
        for (int kv = 0; kv < 4; kv++) {
            unsigned vb[8][2];
#pragma unroll
            for (int jp = 0; jp < 4; jp++)
                ldsm4t(vb[2 * jp][0], vb[2 * jp][1], vb[2 * jp + 1][0], vb[2 * jp + 1][1],
                       vbs + (uint32_t)(((kv * 16 + v_krow) * QP2) + jp * 8 + v_jw) * 4);
#pragma unroll
            for (int j = 0; j < 8; j++)
                mma16(o[j][0], o[j][1], o[j][2], o[j][3],
                      pf[kv][0], pf[kv][1], pf[kv][2], pf[kv][3],
                      vb[j][0], vb[j][1]);
        }
    }

    // normalize + write fp16 (B,T,D)
    const float inv0 = 1.0f / l_run[0];
    const float inv1 = 1.0f / l_run[1];
#pragma unroll
    for (int j = 0; j < 8; j++) {
        const int d = h * DHX + j * 8 + t * 2;
        size_t r0 = ((size_t)b * TT + q0 + qb + g) * DD + d;
        size_t r1 = r0 + (size_t)8 * DD;
        *(__half2*)&g_ctxh[r0] = __floats2half2_rn(o[j][0] * inv0, o[j][1] * inv0);
        *(__half2*)&g_ctxh[r1] = __floats2half2_rn(o[j][2] * inv1, o[j][3] * inv1);
    }
}

// ---------------------------------------------------------------------------
// kernel_launch
// ---------------------------------------------------------------------------
extern "C" void kernel_launch(void* const* d_in, const int* in_sizes, int n_in,
                              void* d_out, int out_size)
{
    const float* query = (const float*)d_in[0];
    const float* key_  = (const float*)d_in[1];
    const float* value = (const float*)d_in[2];
    const float* sp    = (const float*)d_in[3];
    const float* edg   = (const float*)d_in[4];
    const unsigned int* mask = (const unsigned int*)d_in[5];
    const float* Wq = (const float*)d_in[6];
    const float* bq = (const float*)d_in[7];
    const float* Wk = (const float*)d_in[8];
    const float* bk = (const float*)d_in[9];
    const float* Wv = (const float*)d_in[10];
    const float* bv = (const float*)d_in[11];
    const float* Wo = (const float*)d_in[12];
    const float* bo = (const float*)d_in[13];
    float* out = (float*)d_out;

    __half *xq, *xk, *xv, *wq, *wk, *wv, *wo, *gq, *gk, *gv, *gctx;
    cudaGetSymbolAddress((void**)&xq, g_xq);
    cudaGetSymbolAddress((void**)&xk, g_xk);
    cudaGetSymbolAddress((void**)&xv, g_xv);
    cudaGetSymbolAddress((void**)&wq, g_wq);
    cudaGetSymbolAddress((void**)&wk, g_wk);
    cudaGetSymbolAddress((void**)&wv, g_wv);
    cudaGetSymbolAddress((void**)&wo, g_wo);
    cudaGetSymbolAddress((void**)&gq, g_qh);
    cudaGetSymbolAddress((void**)&gk, g_kh);
    cudaGetSymbolAddress((void**)&gv, g_vh);
    cudaGetSymbolAddress((void**)&gctx, g_ctxh);
    float* gb; cudaGetSymbolAddress((void**)&gb, g_bias);

    dim3 gin(MROWS * DD / 4 / 256, 1, 3);
    to_half3<<<gin, 256>>>((const float4*)query, (const float4*)key_, (const float4*)value,
                           (uint2*)xq, (uint2*)xk, (uint2*)xv);
    dim3 gw(DD * DD / 4 / 256, 1, 4);
    to_half4<<<gw, 256>>>((const float4*)Wq, (const float4*)Wk, (const float4*)Wv, (const float4*)Wo,
                          (uint2*)wq, (uint2*)wk, (uint2*)wv, (uint2*)wo);

    cudaFuncSetAttribute(gemm_ha<0>, cudaFuncAttributeMaxDynamicSharedMemorySize, GSM);
    cudaFuncSetAttribute(gemm_ha<1>, cudaFuncAttributeMaxDynamicSharedMemorySize, GSM);
    cudaFuncSetAttribute(attn_h, cudaFuncAttributeMaxDynamicSharedMemorySize, ASMEM);

    // QKV projections (z=0..2) + bias fusion co-scheduled as z=3
    dim3 grid_qkv(DD / 128, MROWS / 128, 4);
    gemm_ha<0><<<grid_qkv, 256, GSM>>>(xq, xk, xv, wq, wk, wv,
                                       bq, bk, bv, gq, gk, gv,
                                       (const float4*)sp, (const float4*)edg, mask, (float4*)gb);

    dim3 attn_grid(TT / 64, HH, BB);   // (16, 16, 8) = 2048 blocks
    attn_h<<<attn_grid, 128, ASMEM>>>(gb);

    dim3 grid_o(DD / 128, MROWS / 128, 1);
    gemm_ha<1><<<grid_o, 256, GSM>>>(gctx, gctx, gctx, wo, wo, wo,
                                     bo, bo, bo, out, out, out,
                                     nullptr, nullptr, nullptr, nullptr);
}

// round 15
// speedup vs baseline: 1.0160x; 1.0160x over previous
#include <cuda_runtime.h>
#include <cuda_fp16.h>
#include <cstdint>

#define BB 8
#define TT 1024
#define DD 1024
#define HH 16
#define DHX 64
#define MROWS (BB*TT)   // 8192

// fp16 scratch
__device__ __half g_xq[MROWS * DD];
__device__ __half g_xk[MROWS * DD];
__device__ __half g_xv[MROWS * DD];
__device__ __half g_wq[DD * DD];
__device__ __half g_wk[DD * DD];
__device__ __half g_wv[DD * DD];
__device__ __half g_wo[DD * DD];
__device__ __half g_qh[MROWS * DD];   // (B,H,T,DH)
__device__ __half g_kh[MROWS * DD];
__device__ __half g_vh[MROWS * DD];
__device__ __half g_ctxh[MROWS * DD]; // (B,T,D)
__device__ float  g_bias[BB * TT * TT]; // sp+ed, masked -> -1e30

// ---------------------------------------------------------------------------
// helpers
// ---------------------------------------------------------------------------
__device__ __forceinline__ unsigned packh2(float lo, float hi) {
    __half2 h = __floats2half2_rn(lo, hi);
    return *reinterpret_cast<unsigned*>(&h);
}
__device__ __forceinline__ uint32_t smem_u32(const void* p) {
    uint32_t a;
    asm("{ .reg .u64 t; cvta.to.shared.u64 t, %1; cvt.u32.u64 %0, t; }" : "=r"(a) : "l"(p));
    return a;
}
__device__ __forceinline__ void ldsm4(unsigned& r0, unsigned& r1, unsigned& r2, unsigned& r3,
                                      uint32_t addr) {
    asm volatile("ldmatrix.sync.aligned.m8n8.x4.shared.b16 {%0,%1,%2,%3}, [%4];"
                 : "=r"(r0), "=r"(r1), "=r"(r2), "=r"(r3) : "r"(addr));
}
__device__ __forceinline__ void ldsm4t(unsigned& r0, unsigned& r1, unsigned& r2, unsigned& r3,
                                       uint32_t addr) {
    asm volatile("ldmatrix.sync.aligned.m8n8.x4.trans.shared.b16 {%0,%1,%2,%3}, [%4];"
                 : "=r"(r0), "=r"(r1), "=r"(r2), "=r"(r3) : "r"(addr));
}
__device__ __forceinline__ void mma16(float& c0, float& c1, float& c2, float& c3,
                                      unsigned a0, unsigned a1, unsigned a2, unsigned a3,
                                      unsigned b0, unsigned b1) {
    asm("mma.sync.aligned.m16n8k16.row.col.f32.f16.f16.f32 "
        "{%0,%1,%2,%3}, {%4,%5,%6,%7}, {%8,%9}, {%0,%1,%2,%3};"
        : "+f"(c0), "+f"(c1), "+f"(c2), "+f"(c3)
        : "r"(a0), "r"(a1), "r"(a2), "r"(a3), "r"(b0), "r"(b1));
}
#define CP16(dst, src) \
    asm volatile("cp.async.cg.shared.global [%0], [%1], 16;" :: "r"(dst), "l"(src))
#define CP_COMMIT() asm volatile("cp.async.commit_group;" ::: "memory")
#define CP_WAIT1()  asm volatile("cp.async.wait_group 1;" ::: "memory")
#define PREF_L2(p)  asm volatile("prefetch.global.L2 [%0];" :: "l"(p))

// ---------------------------------------------------------------------------
// f32 -> fp16 conversion, single launch: z 0..2 = inputs (8192 blocks),
// z 3..6 = weights (first 1024 blocks active, rest early-return)
// ---------------------------------------------------------------------------
__global__ __launch_bounds__(256)
void to_half_all(const float4* __restrict__ s0, const float4* __restrict__ s1,
                 const float4* __restrict__ s2, const float4* __restrict__ s3,
                 const float4* __restrict__ s4, const float4* __restrict__ s5,
                 const float4* __restrict__ s6,
                 uint2* __restrict__ d0, uint2* __restrict__ d1, uint2* __restrict__ d2,
                 uint2* __restrict__ d3, uint2* __restrict__ d4, uint2* __restrict__ d5,
                 uint2* __restrict__ d6)
{
    const int z = blockIdx.z;
    if (z >= 3 && blockIdx.x >= (DD * DD / 4 / 256)) return;
    const float4* s; uint2* d;
    switch (z) {
        case 0: s = s0; d = d0; break;
        case 1: s = s1; d = d1; break;
        case 2: s = s2; d = d2; break;
        case 3: s = s3; d = d3; break;
        case 4: s = s4; d = d4; break;
        case 5: s = s5; d = d5; break;
        default: s = s6; d = d6; break;
    }
    const int i = blockIdx.x * 256 + threadIdx.x;
    float4 v = s[i];
    d[i] = make_uint2(packh2(v.x, v.y), packh2(v.z, v.w));
}

// ---------------------------------------------------------------------------
// fp16 cp.async GEMM (unchanged from R13): C[8192,1024] = A @ W + bias
// MODE 0: z in {0,1,2} = QKV slices; z==3 = bias-fusion slice.
// MODE 1: f32 row-major out.
// ---------------------------------------------------------------------------
#define AP2 36
#define BP2 68
#define ASTG (128 * AP2)
#define BSTG (64 * BP2)
#define GSM  (3 * (ASTG + BSTG) * 4)   // 107520 bytes

template<int MODE>
__global__ __launch_bounds__(256, 2)
void gemm_ha(const __half* __restrict__ A0, const __half* __restrict__ A1, const __half* __restrict__ A2,
             const __half* __restrict__ W0, const __half* __restrict__ W1, const __half* __restrict__ W2,
             const float* __restrict__ bp0, const float* __restrict__ bp1, const float* __restrict__ bp2,
             void* __restrict__ O0, void* __restrict__ O1, void* __restrict__ O2,
             const float4* __restrict__ sp4, const float4* __restrict__ ed4,
             const unsigned* __restrict__ mask, float4* __restrict__ bias_out)
{
    const int tid = threadIdx.x;

    if (MODE == 0 && blockIdx.z == 3) {
        const int base_i = (blockIdx.y * 8 + blockIdx.x) * 256 + tid;
#pragma unroll
        for (int it = 0; it < 16; it++) {
            const int idx = base_i + it * 131072;
            const int b = idx >> 18;
            const int e4 = idx & 262143;
            const int col = (e4 & 255) << 2;
            const uint4 mk = *(const uint4*)&mask[b * TT + col];
            const float4 s = sp4[idx];
            const float4 e = ed4[idx];
            float4 o;
            o.x = mk.x ? -1e30f : (s.x + e.x);
            o.y = mk.y ? -1e30f : (s.y + e.y);
            o.z = mk.z ? -1e30f : (s.z + e.z);
            o.w = mk.w ? -1e30f : (s.w + e.w);
            bias_out[idx] = o;
        }
        return;
    }

    extern __shared__ __align__(16) unsigned smw[];
    const uint32_t base = smem_u32(smw);

    const int lane = tid & 31;
    const int warp = tid >> 5;
    const int g = lane >> 2;
    const int t = lane & 3;
    const int wm = warp >> 1;
    const int wn = warp & 1;
    const int m0 = blockIdx.y * 128;
    const int n0 = blockIdx.x * 128;

    const __half* A = A0; const __half* W = W0; const float* bias = bp0; void* out = O0;
    if (MODE == 0) {
        if (blockIdx.z == 1) { A = A1; W = W1; bias = bp1; out = O1; }
        else if (blockIdx.z == 2) { A = A2; W = W2; bias = bp2; out = O2; }
    }

    const int a_row = (lane & 7) + ((lane >> 3) & 1) * 8;
    const int a_kw  = (lane >> 4) * 4;
    const int b_krow = (lane & 7) + ((lane >> 3) & 1) * 8;
    const int b_j4   = (lane >> 4) * 4;

    auto aw = [&](int s) { return base + (uint32_t)(s * ASTG) * 4; };
    auto bw = [&](int s) { return base + (uint32_t)(3 * ASTG + s * BSTG) * 4; };

    auto issue_stage = [&](int kt, int s) {
        const int k0 = kt * 64;
        const uint32_t ab = aw(s), bb = bw(s);
#pragma unroll
        for (int it = 0; it < 4; it++) {
            int idx = tid + it * 256;
            int m = idx >> 3, ch = idx & 7;
            CP16(ab + (uint32_t)(m * AP2 + ch * 4) * 4,
                 &A[(size_t)(m0 + m) * DD + k0 + ch * 8]);
        }
#pragma unroll
        for (int it = 0; it < 4; it++) {
            int idx = tid + it * 256;
            int kk = idx >> 4, c = idx & 15;
            CP16(bb + (uint32_t)(kk * BP2 + c * 4) * 4,
                 &W[(size_t)(k0 + kk) * DD + n0 + c * 8]);
        }
    };

    issue_stage(0, 0); CP_COMMIT();
    issue_stage(1, 1); CP_COMMIT();

    float acc[2][8][4];
#pragma unroll
    for (int i = 0; i < 2; i++)
#pragma unroll
        for (int j = 0; j < 8; j++)
#pragma unroll
            for (int c = 0; c < 4; c++) acc[i][j][c] = 0.0f;

    for (int kt = 0; kt < 16; kt++) {
        CP_WAIT1();
        __syncthreads();
        if (kt + 2 < 16) issue_stage(kt + 2, (kt + 2) % 3);
        CP_COMMIT();

        const int s = kt % 3;
        const uint32_t as = aw(s), bs = bw(s);

#pragma unroll
        for (int ks = 0; ks < 4; ks++) {
            unsigned af[2][4];
#pragma unroll
            for (int i = 0; i < 2; i++)
                ldsm4(af[i][0], af[i][1], af[i][2], af[i][3],
                      as + (uint32_t)(((wm * 32 + i * 16 + a_row) * AP2) + ks * 8 + a_kw) * 4);
            unsigned bf[8][2];
#pragma unroll
            for (int jp = 0; jp < 4; jp++)
                ldsm4t(bf[2 * jp][0], bf[2 * jp][1], bf[2 * jp + 1][0], bf[2 * jp + 1][1],
                       bs + (uint32_t)(((ks * 16 + b_krow) * BP2) + wn * 32 + jp * 8 + b_j4) * 4);
#pragma unroll
            for (int i = 0; i < 2; i++)
#pragma unroll
                for (int j = 0; j < 8; j++)
                    mma16(acc[i][j][0], acc[i][j][1], acc[i][j][2], acc[i][j][3],
                          af[i][0], af[i][1], af[i][2], af[i][3],
                          bf[j][0], bf[j][1]);
        }
    }

#pragma unroll
    for (int i = 0; i < 2; i++) {
#pragma unroll
        for (int j = 0; j < 8; j++) {
            const int n = n0 + wn * 64 + j * 8 + t * 2;
            const float2 bb = *(const float2*)&bias[n];
#pragma unroll
            for (int h2 = 0; h2 < 2; h2++) {
                const int m = m0 + wm * 32 + i * 16 + g + h2 * 8;
                float vx = acc[i][j][h2 * 2 + 0] + bb.x;
                float vy = acc[i][j][h2 * 2 + 1] + bb.y;
                if (MODE == 0) {
                    int bidx = m >> 10, tt = m & 1023;
                    int hh = n >> 6, d = n & 63;
                    __half2 hv = __floats2half2_rn(vx, vy);
                    *(__half2*)&((__half*)out)[(((size_t)(bidx * HH + hh) << 10) + tt) * DHX + d] = hv;
                } else {
                    *(float2*)&((float*)out)[(size_t)m * DD + n] = make_float2(vx, vy);
                }
            }
        }
    }
}

// ---------------------------------------------------------------------------
// Fused flash attention — EXACT R13/R10 body (fastest measured variant):
// 128-row q-tile, 4 warps x 32 q-rows, fp16 mma + 3-stage cp.async K/V +
// bias L2 prefetch + __expf softmax.
// ---------------------------------------------------------------------------
#define QP2 36
#define QW  (128 * QP2)
#define KVW (64 * QP2)
#define ASMEM ((QW + 3 * 2 * KVW) * 4)   // 73728 bytes

__global__ __launch_bounds__(128)
void attn_h(const float* __restrict__ gb)
{
    extern __shared__ __align__(16) unsigned smw[];
    const uint32_t base = smem_u32(smw);
    unsigned* Q2 = smw;

    const int tid  = threadIdx.x;
    const int lane = tid & 31;
    const int warp = tid >> 5;
    const int g = lane >> 2;
    const int t = lane & 3;
    const int q0 = blockIdx.x * 128;
    const int h  = blockIdx.y;
    const int b  = blockIdx.z;
    const int qb = warp * 32;

    const __half* Qg = g_qh + (size_t)(b * HH + h) * TT * DHX;
    const __half* Kg = g_kh + (size_t)(b * HH + h) * TT * DHX;
    const __half* Vg = g_vh + (size_t)(b * HH + h) * TT * DHX;
    const float* gbrow = &gb[((size_t)b * TT + q0 + tid) * TT];

    const uint32_t sQ = base;
    auto sK = [&](int s) { return base + (uint32_t)(QW + s * 2 * KVW) * 4; };
    auto sV = [&](int s) { return base + (uint32_t)(QW + s * 2 * KVW + KVW) * 4; };

    const int a_row = (lane & 7) + ((lane >> 3) & 1) * 8;
    const int a_kw  = (lane >> 4) * 4;
    const int k_row = (lane & 7) + ((lane >> 4) & 1) * 8;
    const int k_kw  = ((lane >> 3) & 1) * 4;
    const int v_krow = (lane & 7) + ((lane >> 3) & 1) * 8;
    const int v_jw   = (lane >> 4) * 4;

    auto issue_kv = [&](int kt, int s) {
        const int k0 = kt * 64;
        const uint32_t kb = sK(s), vb = sV(s);
#pragma unroll
        for (int it = 0; it < 4; it++) {
            int idx = tid + it * 128;
            int r = idx >> 3, c = idx & 7;
            CP16(kb + (uint32_t)(r * QP2 + c * 4) * 4, &Kg[(size_t)(k0 + r) * DHX + c * 8]);
            CP16(vb + (uint32_t)(r * QP2 + c * 4) * 4, &Vg[(size_t)(k0 + r) * DHX + c * 8]);
        }
    };

#pragma unroll
    for (int it = 0; it < 8; it++) {
        int idx = tid + it * 128;
        int r = idx >> 3, u = idx & 7;
        uint4 qv = *(const uint4*)&Qg[(size_t)(q0 + r) * DHX + u * 8];
        *(uint4*)&Q2[r * QP2 + u * 4] = qv;
    }
    PREF_L2(gbrow);
    PREF_L2(gbrow + 32);
    issue_kv(0, 0); CP_COMMIT();
    issue_kv(1, 1); CP_COMMIT();
    __syncthreads();

    unsigned qf[2][4][4];
#pragma unroll
    for (int mt = 0; mt < 2; mt++)
#pragma unroll
        for (int ks = 0; ks < 4; ks++)
            ldsm4(qf[mt][ks][0], qf[mt][ks][1], qf[mt][ks][2], qf[mt][ks][3],
                  sQ + (uint32_t)(((qb + mt * 16 + a_row) * QP2) + ks * 8 + a_kw) * 4);

    float o[2][8][4];
#pragma unroll
    for (int mt = 0; mt < 2; mt++)
#pragma unroll
        for (int j = 0; j < 8; j++)
#pragma unroll
            for (int c = 0; c < 4; c++) o[mt][j][c] = 0.0f;
    float m_run[2][2] = {{-3e38f, -3e38f}, {-3e38f, -3e38f}};
    float l_run[2][2] = {{0.0f, 0.0f}, {0.0f, 0.0f}};

    for (int kt = 0; kt < 16; kt++) {
        const int k0 = kt * 64;
        CP_WAIT1();
        __syncthreads();
        if (kt + 2 < 16) issue_kv(kt + 2, (kt + 2) % 3);
        CP_COMMIT();

        if (kt + 1 < 16) {
            PREF_L2(gbrow + (kt + 1) * 64);
            PREF_L2(gbrow + (kt + 1) * 64 + 32);
        }

        const int s = kt % 3;
        const uint32_t kbs = sK(s), vbs = sV(s);

        // S = Q K^T
        float sc[2][8][4];
#pragma unroll
        for (int mt = 0; mt < 2; mt++)
#pragma unroll
            for (int j = 0; j < 8; j++)
#pragma unroll
                for (int c = 0; c < 4; c++) sc[mt][j][c] = 0.0f;

#pragma unroll
        for (int ks = 0; ks < 4; ks++) {
            unsigned kb[8][2];
#pragma unroll
            for (int jp = 0; jp < 4; jp++)
                ldsm4(kb[2 * jp][0], kb[2 * jp][1], kb[2 * jp + 1][0], kb[2 * jp + 1][1],
                      kbs + (uint32_t)(((jp * 16 + k_row) * QP2) + ks * 8 + k_kw) * 4);
#pragma unroll
            for (int mt = 0; mt < 2; mt++)
#pragma unroll
                for (int j = 0; j < 8; j++)
                    mma16(sc[mt][j][0], sc[mt][j][1], sc[mt][j][2], sc[mt][j][3],
                          qf[mt][ks][0], qf[mt][ks][1], qf[mt][ks][2], qf[mt][ks][3],
                          kb[j][0], kb[j][1]);
        }

        // scale + fused bias
#pragma unroll
        for (int mt = 0; mt < 2; mt++)
#pragma unroll
            for (int j = 0; j < 8; j++) {
                const int col = k0 + j * 8 + t * 2;
                const size_t i0 = ((size_t)b * TT + (q0 + qb + mt * 16 + g)) * TT + col;
                float2 b0 = *(const float2*)&gb[i0];
                float2 b1 = *(const float2*)&gb[i0 + (size_t)8 * TT];
                sc[mt][j][0] = sc[mt][j][0] * 0.125f + b0.x;
                sc[mt][j][1] = sc[mt][j][1] * 0.125f + b0.y;
                sc[mt][j][2] = sc[mt][j][2] * 0.125f + b1.x;
                sc[mt][j][3] = sc[mt][j][3] * 0.125f + b1.y;
            }

        // online softmax
#pragma unroll
        for (int mt = 0; mt < 2; mt++)
#pragma unroll
            for (int r = 0; r < 2; r++) {
                float mx = -3e38f;
#pragma unroll
                for (int j = 0; j < 8; j++)
                    mx = fmaxf(mx, fmaxf(sc[mt][j][2 * r], sc[mt][j][2 * r + 1]));
                mx = fmaxf(mx, __shfl_xor_sync(0xffffffffu, mx, 1));
                mx = fmaxf(mx, __shfl_xor_sync(0xffffffffu, mx, 2));
                float m_new = fmaxf(m_run[mt][r], mx);
                float alpha = __expf(m_run[mt][r] - m_new);
                m_run[mt][r] = m_new;
                float ls = 0.0f;
#pragma unroll
                for (int j = 0; j < 8; j++) {
                    float p0 = __expf(sc[mt][j][2 * r] - m_new);
                    float p1 = __expf(sc[mt][j][2 * r + 1] - m_new);
                    sc[mt][j][2 * r] = p0; sc[mt][j][2 * r + 1] = p1;
                    ls += p0 + p1;
                }
                ls += __shfl_xor_sync(0xffffffffu, ls, 1);
                ls += __shfl_xor_sync(0xffffffffu, ls, 2);
                l_run[mt][r] = l_run[mt][r] * alpha + ls;
#pragma unroll
                for (int j = 0; j < 8; j++) {
                    o[mt][j][2 * r] *= alpha;
                    o[mt][j][2 * r + 1] *= alpha;
                }
            }

        // pack P into A fragments in registers
        unsigned pf[2][4][4];
#pragma unroll
        for (int mt = 0; mt < 2; mt++)
#pragma unroll
            for (int c = 0; c < 4; c++) {
                pf[mt][c][0] = packh2(sc[mt][2 * c][0], sc[mt][2 * c][1]);
                pf[mt][c][1] = packh2(sc[mt][2 * c][2], sc[mt][2 * c][3]);
                pf[mt][c][2] = packh2(sc[mt][2 * c + 1][0], sc[mt][2 * c + 1][1]);
                pf[mt][c][3] = packh2(sc[mt][2 * c + 1][2], sc[mt][2 * c + 1][3]);
            }

        // O += P @ V
#pragma unroll
        for (int kv = 0; kv < 4; kv++) {
            unsigned vb[8][2];
#pragma unroll
            for (int jp = 0; jp < 4; jp++)
                ldsm4t(vb[2 * jp][0], vb[2 * jp][1], vb[2 * jp + 1][0], vb[2 * jp + 1][1],
                       vbs + (uint32_t)(((kv * 16 + v_krow) * QP2) + jp * 8 + v_jw) * 4);
#pragma unroll
            for (int mt = 0; mt < 2; mt++)
#pragma unroll
                for (int j = 0; j < 8; j++)
                    mma16(o[mt][j][0], o[mt][j][1], o[mt][j][2], o[mt][j][3],
                          pf[mt][kv][0], pf[mt][kv][1], pf[mt][kv][2], pf[mt][kv][3],
                          vb[j][0], vb[j][1]);
        }
    }

    // normalize + write fp16 (B,T,D)
#pragma unroll
    for (int mt = 0; mt < 2; mt++) {
        const float inv0 = 1.0f / l_run[mt][0];
        const float inv1 = 1.0f / l_run[mt][1];
#pragma unroll
        for (int j = 0; j < 8; j++) {
            const int d = h * DHX + j * 8 + t * 2;
            size_t r0 = ((size_t)b * TT + q0 + qb + mt * 16 + g) * DD + d;
            size_t r1 = r0 + (size_t)8 * DD;
            *(__half2*)&g_ctxh[r0] = __floats2half2_rn(o[mt][j][0] * inv0, o[mt][j][1] * inv0);
            *(__half2*)&g_ctxh[r1] = __floats2half2_rn(o[mt][j][2] * inv1, o[mt][j][3] * inv1);
        }
    }
}

// ---------------------------------------------------------------------------
// kernel_launch
// ---------------------------------------------------------------------------
extern "C" void kernel_launch(void* const* d_in, const int* in_sizes, int n_in,
                              void* d_out, int out_size)
{
    const float* query = (const float*)d_in[0];
    const float* key_  = (const float*)d_in[1];
    const float* value = (const float*)d_in[2];
    const float* sp    = (const float*)d_in[3];
    const float* edg   = (const float*)d_in[4];
    const unsigned int* mask = (const unsigned int*)d_in[5];
    const float* Wq = (const float*)d_in[6];
    const float* bq = (const float*)d_in[7];
    const float* Wk = (const float*)d_in[8];
    const float* bk = (const float*)d_in[9];
    const float* Wv = (const float*)d_in[10];
    const float* bv = (const float*)d_in[11];
    const float* Wo = (const float*)d_in[12];
    const float* bo = (const float*)d_in[13];
    float* out = (float*)d_out;

    __half *xq, *xk, *xv, *wq, *wk, *wv, *wo, *gq, *gk, *gv, *gctx;
    cudaGetSymbolAddress((void**)&xq, g_xq);
    cudaGetSymbolAddress((void**)&xk, g_xk);
    cudaGetSymbolAddress((void**)&xv, g_xv);
    cudaGetSymbolAddress((void**)&wq, g_wq);
    cudaGetSymbolAddress((void**)&wk, g_wk);
    cudaGetSymbolAddress((void**)&wv, g_wv);
    cudaGetSymbolAddress((void**)&wo, g_wo);
    cudaGetSymbolAddress((void**)&gq, g_qh);
    cudaGetSymbolAddress((void**)&gk, g_kh);
    cudaGetSymbolAddress((void**)&gv, g_vh);
    cudaGetSymbolAddress((void**)&gctx, g_ctxh);
    float* gb; cudaGetSymbolAddress((void**)&gb, g_bias);

    // all f32->fp16 conversions in ONE launch (z 0..2 inputs, z 3..6 weights)
    dim3 gcv(MROWS * DD / 4 / 256, 1, 7);   // (8192, 1, 7)
    to_half_all<<<gcv, 256>>>((const float4*)query, (const float4*)key_, (const float4*)value,
                              (const float4*)Wq, (const float4*)Wk, (const float4*)Wv, (const float4*)Wo,
                              (uint2*)xq, (uint2*)xk, (uint2*)xv,
                              (uint2*)wq, (uint2*)wk, (uint2*)wv, (uint2*)wo);

    cudaFuncSetAttribute(gemm_ha<0>, cudaFuncAttributeMaxDynamicSharedMemorySize, GSM);
    cudaFuncSetAttribute(gemm_ha<1>, cudaFuncAttributeMaxDynamicSharedMemorySize, GSM);
    cudaFuncSetAttribute(attn_h, cudaFuncAttributeMaxDynamicSharedMemorySize, ASMEM);

    // QKV projections (z=0..2) + bias fusion co-scheduled as z=3
    dim3 grid_qkv(DD / 128, MROWS / 128, 4);
    gemm_ha<0><<<grid_qkv, 256, GSM>>>(xq, xk, xv, wq, wk, wv,
                                       bq, bk, bv, gq, gk, gv,
                                       (const float4*)sp, (const float4*)edg, mask, (float4*)gb);

    dim3 attn_grid(TT / 128, HH, BB);   // (8, 16, 8)
    attn_h<<<attn_grid, 128, ASMEM>>>(gb);

    dim3 grid_o(DD / 128, MROWS / 128, 1);
    gemm_ha<1><<<grid_o, 256, GSM>>>(gctx, gctx, gctx, wo, wo, wo,
                                     bo, bo, bo, out, out, out,
                                     nullptr, nullptr, nullptr, nullptr);
}

// round 16
// speedup vs baseline: 1.0326x; 1.0163x over previous
#include <cuda_runtime.h>
#include <cuda_fp16.h>
#include <cstdint>

#define BB 8
#define TT 1024
#define DD 1024
#define HH 16
#define DHX 64
#define MROWS (BB*TT)   // 8192

// fp16 scratch
__device__ __half g_xq[MROWS * DD];
__device__ __half g_xk[MROWS * DD];
__device__ __half g_xv[MROWS * DD];
__device__ __half g_wq[DD * DD];
__device__ __half g_wk[DD * DD];
__device__ __half g_wv[DD * DD];
__device__ __half g_wo[DD * DD];
__device__ __half g_qh[MROWS * DD];   // (B,H,T,DH)
__device__ __half g_kh[MROWS * DD];
__device__ __half g_vh[MROWS * DD];
__device__ __half g_ctxh[MROWS * DD]; // (B,T,D)
__device__ float  g_bias[BB * TT * TT]; // sp+ed, masked -> -1e30

// ---------------------------------------------------------------------------
// helpers
// ---------------------------------------------------------------------------
__device__ __forceinline__ unsigned packh2(float lo, float hi) {
    __half2 h = __floats2half2_rn(lo, hi);
    return *reinterpret_cast<unsigned*>(&h);
}
__device__ __forceinline__ uint32_t smem_u32(const void* p) {
    uint32_t a;
    asm("{ .reg .u64 t; cvta.to.shared.u64 t, %1; cvt.u32.u64 %0, t; }" : "=r"(a) : "l"(p));
    return a;
}
__device__ __forceinline__ void ldsm4(unsigned& r0, unsigned& r1, unsigned& r2, unsigned& r3,
                                      uint32_t addr) {
    asm volatile("ldmatrix.sync.aligned.m8n8.x4.shared.b16 {%0,%1,%2,%3}, [%4];"
                 : "=r"(r0), "=r"(r1), "=r"(r2), "=r"(r3) : "r"(addr));
}
__device__ __forceinline__ void ldsm4t(unsigned& r0, unsigned& r1, unsigned& r2, unsigned& r3,
                                       uint32_t addr) {
    asm volatile("ldmatrix.sync.aligned.m8n8.x4.trans.shared.b16 {%0,%1,%2,%3}, [%4];"
                 : "=r"(r0), "=r"(r1), "=r"(r2), "=r"(r3) : "r"(addr));
}
__device__ __forceinline__ void mma16(float& c0, float& c1, float& c2, float& c3,
                                      unsigned a0, unsigned a1, unsigned a2, unsigned a3,
                                      unsigned b0, unsigned b1) {
    asm("mma.sync.aligned.m16n8k16.row.col.f32.f16.f16.f32 "
        "{%0,%1,%2,%3}, {%4,%5,%6,%7}, {%8,%9}, {%0,%1,%2,%3};"
        : "+f"(c0), "+f"(c1), "+f"(c2), "+f"(c3)
        : "r"(a0), "r"(a1), "r"(a2), "r"(a3), "r"(b0), "r"(b1));
}
#define CP16(dst, src) \
    asm volatile("cp.async.cg.shared.global [%0], [%1], 16;" :: "r"(dst), "l"(src))
#define CP_COMMIT() asm volatile("cp.async.commit_group;" ::: "memory")
#define CP_WAIT1()  asm volatile("cp.async.wait_group 1;" ::: "memory")
#define CP_WAIT2()  asm volatile("cp.async.wait_group 2;" ::: "memory")
#define PREF_L2(p)  asm volatile("prefetch.global.L2 [%0];" :: "l"(p))

// ---------------------------------------------------------------------------
// f32 -> fp16 conversion, z-batched (R13 layout: two launches, no empty blocks)
// ---------------------------------------------------------------------------
__global__ __launch_bounds__(256)
void to_half3(const float4* __restrict__ s0, const float4* __restrict__ s1,
              const float4* __restrict__ s2,
              uint2* __restrict__ d0, uint2* __restrict__ d1, uint2* __restrict__ d2)
{
    const float4* s = (blockIdx.z == 0) ? s0 : (blockIdx.z == 1) ? s1 : s2;
    uint2* d = (blockIdx.z == 0) ? d0 : (blockIdx.z == 1) ? d1 : d2;
    const int i = blockIdx.x * 256 + threadIdx.x;
    float4 v = s[i];
    d[i] = make_uint2(packh2(v.x, v.y), packh2(v.z, v.w));
}
__global__ __launch_bounds__(256)
void to_half4(const float4* __restrict__ s0, const float4* __restrict__ s1,
              const float4* __restrict__ s2, const float4* __restrict__ s3,
              uint2* __restrict__ d0, uint2* __restrict__ d1,
              uint2* __restrict__ d2, uint2* __restrict__ d3)
{
    const float4* s = (blockIdx.z == 0) ? s0 : (blockIdx.z == 1) ? s1 :
                      (blockIdx.z == 2) ? s2 : s3;
    uint2* d = (blockIdx.z == 0) ? d0 : (blockIdx.z == 1) ? d1 :
               (blockIdx.z == 2) ? d2 : d3;
    const int i = blockIdx.x * 256 + threadIdx.x;
    float4 v = s[i];
    d[i] = make_uint2(packh2(v.x, v.y), packh2(v.z, v.w));
}

// ---------------------------------------------------------------------------
// fp16 cp.async GEMM (unchanged from R13): C[8192,1024] = A @ W + bias
// MODE 0: z in {0,1,2} = QKV slices; z==3 = bias-fusion slice.
// MODE 1: f32 row-major out.
// ---------------------------------------------------------------------------
#define AP2 36
#define BP2 68
#define ASTG (128 * AP2)
#define BSTG (64 * BP2)
#define GSM  (3 * (ASTG + BSTG) * 4)   // 107520 bytes

template<int MODE>
__global__ __launch_bounds__(256, 2)
void gemm_ha(const __half* __restrict__ A0, const __half* __restrict__ A1, const __half* __restrict__ A2,
             const __half* __restrict__ W0, const __half* __restrict__ W1, const __half* __restrict__ W2,
             const float* __restrict__ bp0, const float* __restrict__ bp1, const float* __restrict__ bp2,
             void* __restrict__ O0, void* __restrict__ O1, void* __restrict__ O2,
             const float4* __restrict__ sp4, const float4* __restrict__ ed4,
             const unsigned* __restrict__ mask, float4* __restrict__ bias_out)
{
    const int tid = threadIdx.x;

    if (MODE == 0 && blockIdx.z == 3) {
        const int base_i = (blockIdx.y * 8 + blockIdx.x) * 256 + tid;
#pragma unroll
        for (int it = 0; it < 16; it++) {
            const int idx = base_i + it * 131072;
            const int b = idx >> 18;
            const int e4 = idx & 262143;
            const int col = (e4 & 255) << 2;
            const uint4 mk = *(const uint4*)&mask[b * TT + col];
            const float4 s = sp4[idx];
            const float4 e = ed4[idx];
            float4 o;
            o.x = mk.x ? -1e30f : (s.x + e.x);
            o.y = mk.y ? -1e30f : (s.y + e.y);
            o.z = mk.z ? -1e30f : (s.z + e.z);
            o.w = mk.w ? -1e30f : (s.w + e.w);
            bias_out[idx] = o;
        }
        return;
    }

    extern __shared__ __align__(16) unsigned smw[];
    const uint32_t base = smem_u32(smw);

    const int lane = tid & 31;
    const int warp = tid >> 5;
    const int g = lane >> 2;
    const int t = lane & 3;
    const int wm = warp >> 1;
    const int wn = warp & 1;
    const int m0 = blockIdx.y * 128;
    const int n0 = blockIdx.x * 128;

    const __half* A = A0; const __half* W = W0; const float* bias = bp0; void* out = O0;
    if (MODE == 0) {
        if (blockIdx.z == 1) { A = A1; W = W1; bias = bp1; out = O1; }
        else if (blockIdx.z == 2) { A = A2; W = W2; bias = bp2; out = O2; }
    }

    const int a_row = (lane & 7) + ((lane >> 3) & 1) * 8;
    const int a_kw  = (lane >> 4) * 4;
    const int b_krow = (lane & 7) + ((lane >> 3) & 1) * 8;
    const int b_j4   = (lane >> 4) * 4;

    auto aw = [&](int s) { return base + (uint32_t)(s * ASTG) * 4; };
    auto bw = [&](int s) { return base + (uint32_t)(3 * ASTG + s * BSTG) * 4; };

    auto issue_stage = [&](int kt, int s) {
        const int k0 = kt * 64;
        const uint32_t ab = aw(s), bb = bw(s);
#pragma unroll
        for (int it = 0; it < 4; it++) {
            int idx = tid + it * 256;
            int m = idx >> 3, ch = idx & 7;
            CP16(ab + (uint32_t)(m * AP2 + ch * 4) * 4,
                 &A[(size_t)(m0 + m) * DD + k0 + ch * 8]);
        }
#pragma unroll
        for (int it = 0; it < 4; it++) {
            int idx = tid + it * 256;
            int kk = idx >> 4, c = idx & 15;
            CP16(bb + (uint32_t)(kk * BP2 + c * 4) * 4,
                 &W[(size_t)(k0 + kk) * DD + n0 + c * 8]);
        }
    };

    issue_stage(0, 0); CP_COMMIT();
    issue_stage(1, 1); CP_COMMIT();

    float acc[2][8][4];
#pragma unroll
    for (int i = 0; i < 2; i++)
#pragma unroll
        for (int j = 0; j < 8; j++)
#pragma unroll
            for (int c = 0; c < 4; c++) acc[i][j][c] = 0.0f;

    for (int kt = 0; kt < 16; kt++) {
        CP_WAIT1();
        __syncthreads();
        if (kt + 2 < 16) issue_stage(kt + 2, (kt + 2) % 3);
        CP_COMMIT();

        const int s = kt % 3;
        const uint32_t as = aw(s), bs = bw(s);

#pragma unroll
        for (int ks = 0; ks < 4; ks++) {
            unsigned af[2][4];
#pragma unroll
            for (int i = 0; i < 2; i++)
                ldsm4(af[i][0], af[i][1], af[i][2], af[i][3],
                      as + (uint32_t)(((wm * 32 + i * 16 + a_row) * AP2) + ks * 8 + a_kw) * 4);
            unsigned bf[8][2];
#pragma unroll
            for (int jp = 0; jp < 4; jp++)
                ldsm4t(bf[2 * jp][0], bf[2 * jp][1], bf[2 * jp + 1][0], bf[2 * jp + 1][1],
                       bs + (uint32_t)(((ks * 16 + b_krow) * BP2) + wn * 32 + jp * 8 + b_j4) * 4);
#pragma unroll
            for (int i = 0; i < 2; i++)
#pragma unroll
                for (int j = 0; j < 8; j++)
                    mma16(acc[i][j][0], acc[i][j][1], acc[i][j][2], acc[i][j][3],
                          af[i][0], af[i][1], af[i][2], af[i][3],
                          bf[j][0], bf[j][1]);
        }
    }

#pragma unroll
    for (int i = 0; i < 2; i++) {
#pragma unroll
        for (int j = 0; j < 8; j++) {
            const int n = n0 + wn * 64 + j * 8 + t * 2;
            const float2 bb = *(const float2*)&bias[n];
#pragma unroll
            for (int h2 = 0; h2 < 2; h2++) {
                const int m = m0 + wm * 32 + i * 16 + g + h2 * 8;
                float vx = acc[i][j][h2 * 2 + 0] + bb.x;
                float vy = acc[i][j][h2 * 2 + 1] + bb.y;
                if (MODE == 0) {
                    int bidx = m >> 10, tt = m & 1023;
                    int hh = n >> 6, d = n & 63;
                    __half2 hv = __floats2half2_rn(vx, vy);
                    *(__half2*)&((__half*)out)[(((size_t)(bidx * HH + hh) << 10) + tt) * DHX + d] = hv;
                } else {
                    *(float2*)&((float*)out)[(size_t)m * DD + n] = make_float2(vx, vy);
                }
            }
        }
    }
}

// ---------------------------------------------------------------------------
// Fused flash attention — R13 body with a 4-stage K/V cp.async ring
// (wait_group 2, prefetch distance 3). Math identical to R13/R10.
// smem: Q 128x36w + 4 stages x [K 64x36w | V 64x36w] = 92160 B (2 CTAs fit).
// ---------------------------------------------------------------------------
#define QP2 36
#define QW  (128 * QP2)
#define KVW (64 * QP2)
#define NSTG 4
#define ASMEM ((QW + NSTG * 2 * KVW) * 4)   // 92160 bytes

__global__ __launch_bounds__(128)
void attn_h(const float* __restrict__ gb)
{
    extern __shared__ __align__(16) unsigned smw[];
    const uint32_t base = smem_u32(smw);
    unsigned* Q2 = smw;

    const int tid  = threadIdx.x;
    const int lane = tid & 31;
    const int warp = tid >> 5;
    const int g = lane >> 2;
    const int t = lane & 3;
    const int q0 = blockIdx.x * 128;
    const int h  = blockIdx.y;
    const int b  = blockIdx.z;
    const int qb = warp * 32;

    const __half* Qg = g_qh + (size_t)(b * HH + h) * TT * DHX;
    const __half* Kg = g_kh + (size_t)(b * HH + h) * TT * DHX;
    const __half* Vg = g_vh + (size_t)(b * HH + h) * TT * DHX;
    const float* gbrow = &gb[((size_t)b * TT + q0 + tid) * TT];

    const uint32_t sQ = base;
    auto sK = [&](int s) { return base + (uint32_t)(QW + s * 2 * KVW) * 4; };
    auto sV = [&](int s) { return base + (uint32_t)(QW + s * 2 * KVW + KVW) * 4; };

    const int a_row = (lane & 7) + ((lane >> 3) & 1) * 8;
    const int a_kw  = (lane >> 4) * 4;
    const int k_row = (lane & 7) + ((lane >> 4) & 1) * 8;
    const int k_kw  = ((lane >> 3) & 1) * 4;
    const int v_krow = (lane & 7) + ((lane >> 3) & 1) * 8;
    const int v_jw   = (lane >> 4) * 4;

    auto issue_kv = [&](int kt, int s) {
        const int k0 = kt * 64;
        const uint32_t kb = sK(s), vb = sV(s);
#pragma unroll
        for (int it = 0; it < 4; it++) {
            int idx = tid + it * 128;
            int r = idx >> 3, c = idx & 7;
            CP16(kb + (uint32_t)(r * QP2 + c * 4) * 4, &Kg[(size_t)(k0 + r) * DHX + c * 8]);
            CP16(vb + (uint32_t)(r * QP2 + c * 4) * 4, &Vg[(size_t)(k0 + r) * DHX + c * 8]);
        }
    };

#pragma unroll
    for (int it = 0; it < 8; it++) {
        int idx = tid + it * 128;
        int r = idx >> 3, u = idx & 7;
        uint4 qv = *(const uint4*)&Qg[(size_t)(q0 + r) * DHX + u * 8];
        *(uint4*)&Q2[r * QP2 + u * 4] = qv;
    }
    PREF_L2(gbrow);
    PREF_L2(gbrow + 32);
    issue_kv(0, 0); CP_COMMIT();
    issue_kv(1, 1); CP_COMMIT();
    issue_kv(2, 2); CP_COMMIT();
    __syncthreads();

    unsigned qf[2][4][4];
#pragma unroll
    for (int mt = 0; mt < 2; mt++)
#pragma unroll
        for (int ks = 0; ks < 4; ks++)
            ldsm4(qf[mt][ks][0], qf[mt][ks][1], qf[mt][ks][2], qf[mt][ks][3],
                  sQ + (uint32_t)(((qb + mt * 16 + a_row) * QP2) + ks * 8 + a_kw) * 4);

    float o[2][8][4];
#pragma unroll
    for (int mt = 0; mt < 2; mt++)
#pragma unroll
        for (int j = 0; j < 8; j++)
#pragma unroll
            for (int c = 0; c < 4; c++) o[mt][j][c] = 0.0f;
    float m_run[2][2] = {{-3e38f, -3e38f}, {-3e38f, -3e38f}};
    float l_run[2][2] = {{0.0f, 0.0f}, {0.0f, 0.0f}};

    for (int kt = 0; kt < 16; kt++) {
        const int k0 = kt * 64;
        CP_WAIT2();
        __syncthreads();
        if (kt + 3 < 16) issue_kv(kt + 3, (kt + 3) % NSTG);
        CP_COMMIT();

        if (kt + 1 < 16) {
            PREF_L2(gbrow + (kt + 1) * 64);
            PREF_L2(gbrow + (kt + 1) * 64 + 32);
        }

        const int s = kt % NSTG;
        const uint32_t kbs = sK(s), vbs = sV(s);

        // S = Q K^T
        float sc[2][8][4];
#pragma unroll
        for (int mt = 0; mt < 2; mt++)
#pragma unroll
            for (int j = 0; j < 8; j++)
#pragma unroll
                for (int c = 0; c < 4; c++) sc[mt][j][c] = 0.0f;

#pragma unroll
        for (int ks = 0; ks < 4; ks++) {
            unsigned kb[8][2];
#pragma unroll
            for (int jp = 0; jp < 4; jp++)
                ldsm4(kb[2 * jp][0], kb[2 * jp][1], kb[2 * jp + 1][0], kb[2 * jp + 1][1],
                      kbs + (uint32_t)(((jp * 16 + k_row) * QP2) + ks * 8 + k_kw) * 4);
#pragma unroll
            for (int mt = 0; mt < 2; mt++)
#pragma unroll
                for (int j = 0; j < 8; j++)
                    mma16(sc[mt][j][0], sc[mt][j][1], sc[mt][j][2], sc[mt][j][3],
                          qf[mt][ks][0], qf[mt][ks][1], qf[mt][ks][2], qf[mt][ks][3],
                          kb[j][0], kb[j][1]);
        }

        // scale + fused bias
#pragma unroll
        for (int mt = 0; mt < 2; mt++)
#pragma unroll
            for (int j = 0; j < 8; j++) {
                const int col = k0 + j * 8 + t * 2;
                const size_t i0 = ((size_t)b * TT + (q0 + qb + mt * 16 + g)) * TT + col;
                float2 b0 = *(const float2*)&gb[i0];
                float2 b1 = *(const float2*)&gb[i0 + (size_t)8 * TT];
                sc[mt][j][0] = sc[mt][j][0] * 0.125f + b0.x;
                sc[mt][j][1] = sc[mt][j][1] * 0.125f + b0.y;
                sc[mt][j][2] = sc[mt][j][2] * 0.125f + b1.x;
                sc[mt][j][3] = sc[mt][j][3] * 0.125f + b1.y;
            }

        // online softmax
#pragma unroll
        for (int mt = 0; mt < 2; mt++)
#pragma unroll
            for (int r = 0; r < 2; r++) {
                float mx = -3e38f;
#pragma unroll
                for (int j = 0; j < 8; j++)
                    mx = fmaxf(mx, fmaxf(sc[mt][j][2 * r], sc[mt][j][2 * r + 1]));
                mx = fmaxf(mx, __shfl_xor_sync(0xffffffffu, mx, 1));
                mx = fmaxf(mx, __shfl_xor_sync(0xffffffffu, mx, 2));
                float m_new = fmaxf(m_run[mt][r], mx);
                float alpha = __expf(m_run[mt][r] - m_new);
                m_run[mt][r] = m_new;
                float ls = 0.0f;
#pragma unroll
                for (int j = 0; j < 8; j++) {
                    float p0 = __expf(sc[mt][j][2 * r] - m_new);
                    float p1 = __expf(sc[mt][j][2 * r + 1] - m_new);
                    sc[mt][j][2 * r] = p0; sc[mt][j][2 * r + 1] = p1;
                    ls += p0 + p1;
                }
                ls += __shfl_xor_sync(0xffffffffu, ls, 1);
                ls += __shfl_xor_sync(0xffffffffu, ls, 2);
                l_run[mt][r] = l_run[mt][r] * alpha + ls;
#pragma unroll
                for (int j = 0; j < 8; j++) {
                    o[mt][j][2 * r] *= alpha;
                    o[mt][j][2 * r + 1] *= alpha;
                }
            }

        // pack P into A fragments in registers
        unsigned pf[2][4][4];
#pragma unroll
        for (int mt = 0; mt < 2; mt++)
#pragma unroll
            for (int c = 0; c < 4; c++) {
                pf[mt][c][0] = packh2(sc[mt][2 * c][0], sc[mt][2 * c][1]);
                pf[mt][c][1] = packh2(sc[mt][2 * c][2], sc[mt][2 * c][3]);
                pf[mt][c][2] = packh2(sc[mt][2 * c + 1][0], sc[mt][2 * c + 1][1]);
                pf[mt][c][3] = packh2(sc[mt][2 * c + 1][2], sc[mt][2 * c + 1][3]);
            }

        // O += P @ V
#pragma unroll
        for (int kv = 0; kv < 4; kv++) {
            unsigned vb[8][2];
#pragma unroll
            for (int jp = 0; jp < 4; jp++)
                ldsm4t(vb[2 * jp][0], vb[2 * jp][1], vb[2 * jp + 1][0], vb[2 * jp + 1][1],
                       vbs + (uint32_t)(((kv * 16 + v_krow) * QP2) + jp * 8 + v_jw) * 4);
#pragma unroll
            for (int mt = 0; mt < 2; mt++)
#pragma unroll
                for (int j = 0; j < 8; j++)
                    mma16(o[mt][j][0], o[mt][j][1], o[mt][j][2], o[mt][j][3],
                          pf[mt][kv][0], pf[mt][kv][1], pf[mt][kv][2], pf[mt][kv][3],
                          vb[j][0], vb[j][1]);
        }
    }

    // normalize + write fp16 (B,T,D)
#pragma unroll
    for (int mt = 0; mt < 2; mt++) {
        const float inv0 = 1.0f / l_run[mt][0];
        const float inv1 = 1.0f / l_run[mt][1];
#pragma unroll
        for (int j = 0; j < 8; j++) {
            const int d = h * DHX + j * 8 + t * 2;
            size_t r0 = ((size_t)b * TT + q0 + qb + mt * 16 + g) * DD + d;
            size_t r1 = r0 + (size_t)8 * DD;
            *(__half2*)&g_ctxh[r0] = __floats2half2_rn(o[mt][j][0] * inv0, o[mt][j][1] * inv0);
            *(__half2*)&g_ctxh[r1] = __floats2half2_rn(o[mt][j][2] * inv1, o[mt][j][3] * inv1);
        }
    }
}

// ---------------------------------------------------------------------------
// kernel_launch
// ---------------------------------------------------------------------------
extern "C" void kernel_launch(void* const* d_in, const int* in_sizes, int n_in,
                              void* d_out, int out_size)
{
    const float* query = (const float*)d_in[0];
    const float* key_  = (const float*)d_in[1];
    const float* value = (const float*)d_in[2];
    const float* sp    = (const float*)d_in[3];
    const float* edg   = (const float*)d_in[4];
    const unsigned int* mask = (const unsigned int*)d_in[5];
    const float* Wq = (const float*)d_in[6];
    const float* bq = (const float*)d_in[7];
    const float* Wk = (const float*)d_in[8];
    const float* bk = (const float*)d_in[9];
    const float* Wv = (const float*)d_in[10];
    const float* bv = (const float*)d_in[11];
    const float* Wo = (const float*)d_in[12];
    const float* bo = (const float*)d_in[13];
    float* out = (float*)d_out;

    __half *xq, *xk, *xv, *wq, *wk, *wv, *wo, *gq, *gk, *gv, *gctx;
    cudaGetSymbolAddress((void**)&xq, g_xq);
    cudaGetSymbolAddress((void**)&xk, g_xk);
    cudaGetSymbolAddress((void**)&xv, g_xv);
    cudaGetSymbolAddress((void**)&wq, g_wq);
    cudaGetSymbolAddress((void**)&wk, g_wk);
    cudaGetSymbolAddress((void**)&wv, g_wv);
    cudaGetSymbolAddress((void**)&wo, g_wo);
    cudaGetSymbolAddress((void**)&gq, g_qh);
    cudaGetSymbolAddress((void**)&gk, g_kh);
    cudaGetSymbolAddress((void**)&gv, g_vh);
    cudaGetSymbolAddress((void**)&gctx, g_ctxh);
    float* gb; cudaGetSymbolAddress((void**)&gb, g_bias);

    dim3 gin(MROWS * DD / 4 / 256, 1, 3);
    to_half3<<<gin, 256>>>((const float4*)query, (const float4*)key_, (const float4*)value,
                           (uint2*)xq, (uint2*)xk, (uint2*)xv);
    dim3 gw(DD * DD / 4 / 256, 1, 4);
    to_half4<<<gw, 256>>>((const float4*)Wq, (const float4*)Wk, (const float4*)Wv, (const float4*)Wo,
                          (uint2*)wq, (uint2*)wk, (uint2*)wv, (uint2*)wo);

    cudaFuncSetAttribute(gemm_ha<0>, cudaFuncAttributeMaxDynamicSharedMemorySize, GSM);
    cudaFuncSetAttribute(gemm_ha<1>, cudaFuncAttributeMaxDynamicSharedMemorySize, GSM);
    cudaFuncSetAttribute(attn_h, cudaFuncAttributeMaxDynamicSharedMemorySize, ASMEM);

    // QKV projections (z=0..2) + bias fusion co-scheduled as z=3
    dim3 grid_qkv(DD / 128, MROWS / 128, 4);
    gemm_ha<0><<<grid_qkv, 256, GSM>>>(xq, xk, xv, wq, wk, wv,
                                       bq, bk, bv, gq, gk, gv,
                                       (const float4*)sp, (const float4*)edg, mask, (float4*)gb);

    dim3 attn_grid(TT / 128, HH, BB);   // (8, 16, 8)
    attn_h<<<attn_grid, 128, ASMEM>>>(gb);

    dim3 grid_o(DD / 128, MROWS / 128, 1);
    gemm_ha<1><<<grid_o, 256, GSM>>>(gctx, gctx, gctx, wo, wo, wo,
                                     bo, bo, bo, out, out, out,
                                     nullptr, nullptr, nullptr, nullptr);
}

// round 17
// speedup vs baseline: 1.0496x; 1.0164x over previous
#include <cuda_runtime.h>
#include <cuda_fp16.h>
#include <cstdint>

#define BB 8
#define TT 1024
#define DD 1024
#define HH 16
#define DHX 64
#define MROWS (BB*TT)   // 8192

// fp16 scratch
__device__ __half g_xq[MROWS * DD];
__device__ __half g_xk[MROWS * DD];
__device__ __half g_xv[MROWS * DD];
__device__ __half g_wq[DD * DD];
__device__ __half g_wk[DD * DD];
__device__ __half g_wv[DD * DD];
__device__ __half g_wo[DD * DD];
__device__ __half g_qh[MROWS * DD];   // (B,H,T,DH)
__device__ __half g_kh[MROWS * DD];
__device__ __half g_vh[MROWS * DD];
__device__ __half g_ctxh[MROWS * DD]; // (B,T,D)
__device__ float  g_bias[BB * TT * TT]; // sp+ed, masked -> -1e30

// ---------------------------------------------------------------------------
// helpers
// ---------------------------------------------------------------------------
__device__ __forceinline__ unsigned packh2(float lo, float hi) {
    __half2 h = __floats2half2_rn(lo, hi);
    return *reinterpret_cast<unsigned*>(&h);
}
__device__ __forceinline__ uint32_t smem_u32(const void* p) {
    uint32_t a;
    asm("{ .reg .u64 t; cvta.to.shared.u64 t, %1; cvt.u32.u64 %0, t; }" : "=r"(a) : "l"(p));
    return a;
}
__device__ __forceinline__ void ldsm4(unsigned& r0, unsigned& r1, unsigned& r2, unsigned& r3,
                                      uint32_t addr) {
    asm volatile("ldmatrix.sync.aligned.m8n8.x4.shared.b16 {%0,%1,%2,%3}, [%4];"
                 : "=r"(r0), "=r"(r1), "=r"(r2), "=r"(r3) : "r"(addr));
}
__device__ __forceinline__ void ldsm4t(unsigned& r0, unsigned& r1, unsigned& r2, unsigned& r3,
                                       uint32_t addr) {
    asm volatile("ldmatrix.sync.aligned.m8n8.x4.trans.shared.b16 {%0,%1,%2,%3}, [%4];"
                 : "=r"(r0), "=r"(r1), "=r"(r2), "=r"(r3) : "r"(addr));
}
__device__ __forceinline__ void mma16(float& c0, float& c1, float& c2, float& c3,
                                      unsigned a0, unsigned a1, unsigned a2, unsigned a3,
                                      unsigned b0, unsigned b1) {
    asm("mma.sync.aligned.m16n8k16.row.col.f32.f16.f16.f32 "
        "{%0,%1,%2,%3}, {%4,%5,%6,%7}, {%8,%9}, {%0,%1,%2,%3};"
        : "+f"(c0), "+f"(c1), "+f"(c2), "+f"(c3)
        : "r"(a0), "r"(a1), "r"(a2), "r"(a3), "r"(b0), "r"(b1));
}
#define CP16(dst, src) \
    asm volatile("cp.async.cg.shared.global [%0], [%1], 16;" :: "r"(dst), "l"(src))
#define CP_COMMIT() asm volatile("cp.async.commit_group;" ::: "memory")
#define CP_WAIT1()  asm volatile("cp.async.wait_group 1;" ::: "memory")
#define CP_WAIT2()  asm volatile("cp.async.wait_group 2;" ::: "memory")
#define PREF_L2(p)  asm volatile("prefetch.global.L2 [%0];" :: "l"(p))

// ---------------------------------------------------------------------------
// f32 -> fp16 conversion, ONE launch, flattened 1-D grid (no empty blocks).
// Slices: 3 inputs of 2^21 float4 each, then 4 weights of 2^18 float4 each.
// ---------------------------------------------------------------------------
#define IN_F4  (MROWS * DD / 4)        // 2097152 = 2^21
#define W_F4   (DD * DD / 4)           // 262144  = 2^18
#define CONV_TOTAL (3 * IN_F4 + 4 * W_F4)   // 7340032 float4
#define CONV_BLOCKS (CONV_TOTAL / 256)      // 28672

__global__ __launch_bounds__(256)
void to_half_flat(const float4* __restrict__ s0, const float4* __restrict__ s1,
                  const float4* __restrict__ s2, const float4* __restrict__ s3,
                  const float4* __restrict__ s4, const float4* __restrict__ s5,
                  const float4* __restrict__ s6,
                  uint2* __restrict__ d0, uint2* __restrict__ d1, uint2* __restrict__ d2,
                  uint2* __restrict__ d3, uint2* __restrict__ d4, uint2* __restrict__ d5,
                  uint2* __restrict__ d6)
{
    const int gid = blockIdx.x * 256 + threadIdx.x;
    const float4* s; uint2* d; int off;
    if (gid < 3 * IN_F4) {
        const int z = gid >> 21;
        off = gid & (IN_F4 - 1);
        s = (z == 0) ? s0 : (z == 1) ? s1 : s2;
        d = (z == 0) ? d0 : (z == 1) ? d1 : d2;
    } else {
        const int w = gid - 3 * IN_F4;
        const int z = w >> 18;
        off = w & (W_F4 - 1);
        s = (z == 0) ? s3 : (z == 1) ? s4 : (z == 2) ? s5 : s6;
        d = (z == 0) ? d3 : (z == 1) ? d4 : (z == 2) ? d5 : d6;
    }
    float4 v = s[off];
    d[off] = make_uint2(packh2(v.x, v.y), packh2(v.z, v.w));
}

// ---------------------------------------------------------------------------
// fp16 cp.async GEMM (unchanged): C[8192,1024] = A @ W + bias
// MODE 0: z in {0,1,2} = QKV slices; z==3 = bias-fusion slice.
// MODE 1: f32 row-major out.
// ---------------------------------------------------------------------------
#define AP2 36
#define BP2 68
#define ASTG (128 * AP2)
#define BSTG (64 * BP2)
#define GSM  (3 * (ASTG + BSTG) * 4)   // 107520 bytes

template<int MODE>
__global__ __launch_bounds__(256, 2)
void gemm_ha(const __half* __restrict__ A0, const __half* __restrict__ A1, const __half* __restrict__ A2,
             const __half* __restrict__ W0, const __half* __restrict__ W1, const __half* __restrict__ W2,
             const float* __restrict__ bp0, const float* __restrict__ bp1, const float* __restrict__ bp2,
             void* __restrict__ O0, void* __restrict__ O1, void* __restrict__ O2,
             const float4* __restrict__ sp4, const float4* __restrict__ ed4,
             const unsigned* __restrict__ mask, float4* __restrict__ bias_out)
{
    const int tid = threadIdx.x;

    if (MODE == 0 && blockIdx.z == 3) {
        const int base_i = (blockIdx.y * 8 + blockIdx.x) * 256 + tid;
#pragma unroll
        for (int it = 0; it < 16; it++) {
            const int idx = base_i + it * 131072;
            const int b = idx >> 18;
            const int e4 = idx & 262143;
            const int col = (e4 & 255) << 2;
            const uint4 mk = *(const uint4*)&mask[b * TT + col];
            const float4 s = sp4[idx];
            const float4 e = ed4[idx];
            float4 o;
            o.x = mk.x ? -1e30f : (s.x + e.x);
            o.y = mk.y ? -1e30f : (s.y + e.y);
            o.z = mk.z ? -1e30f : (s.z + e.z);
            o.w = mk.w ? -1e30f : (s.w + e.w);
            bias_out[idx] = o;
        }
        return;
    }

    extern __shared__ __align__(16) unsigned smw[];
    const uint32_t base = smem_u32(smw);

    const int lane = tid & 31;
    const int warp = tid >> 5;
    const int g = lane >> 2;
    const int t = lane & 3;
    const int wm = warp >> 1;
    const int wn = warp & 1;
    const int m0 = blockIdx.y * 128;
    const int n0 = blockIdx.x * 128;

    const __half* A = A0; const __half* W = W0; const float* bias = bp0; void* out = O0;
    if (MODE == 0) {
        if (blockIdx.z == 1) { A = A1; W = W1; bias = bp1; out = O1; }
        else if (blockIdx.z == 2) { A = A2; W = W2; bias = bp2; out = O2; }
    }

    const int a_row = (lane & 7) + ((lane >> 3) & 1) * 8;
    const int a_kw  = (lane >> 4) * 4;
    const int b_krow = (lane & 7) + ((lane >> 3) & 1) * 8;
    const int b_j4   = (lane >> 4) * 4;

    auto aw = [&](int s) { return base + (uint32_t)(s * ASTG) * 4; };
    auto bw = [&](int s) { return base + (uint32_t)(3 * ASTG + s * BSTG) * 4; };

    auto issue_stage = [&](int kt, int s) {
        const int k0 = kt * 64;
        const uint32_t ab = aw(s), bb = bw(s);
#pragma unroll
        for (int it = 0; it < 4; it++) {
            int idx = tid + it * 256;
            int m = idx >> 3, ch = idx & 7;
            CP16(ab + (uint32_t)(m * AP2 + ch * 4) * 4,
                 &A[(size_t)(m0 + m) * DD + k0 + ch * 8]);
        }
#pragma unroll
        for (int it = 0; it < 4; it++) {
            int idx = tid + it * 256;
            int kk = idx >> 4, c = idx & 15;
            CP16(bb + (uint32_t)(kk * BP2 + c * 4) * 4,
                 &W[(size_t)(k0 + kk) * DD + n0 + c * 8]);
        }
    };

    issue_stage(0, 0); CP_COMMIT();
    issue_stage(1, 1); CP_COMMIT();

    float acc[2][8][4];
#pragma unroll
    for (int i = 0; i < 2; i++)
#pragma unroll
        for (int j = 0; j < 8; j++)
#pragma unroll
            for (int c = 0; c < 4; c++) acc[i][j][c] = 0.0f;

    for (int kt = 0; kt < 16; kt++) {
        CP_WAIT1();
        __syncthreads();
        if (kt + 2 < 16) issue_stage(kt + 2, (kt + 2) % 3);
        CP_COMMIT();

        const int s = kt % 3;
        const uint32_t as = aw(s), bs = bw(s);

#pragma unroll
        for (int ks = 0; ks < 4; ks++) {
            unsigned af[2][4];
#pragma unroll
            for (int i = 0; i < 2; i++)
                ldsm4(af[i][0], af[i][1], af[i][2], af[i][3],
                      as + (uint32_t)(((wm * 32 + i * 16 + a_row) * AP2) + ks * 8 + a_kw) * 4);
            unsigned bf[8][2];
#pragma unroll
            for (int jp = 0; jp < 4; jp++)
                ldsm4t(bf[2 * jp][0], bf[2 * jp][1], bf[2 * jp + 1][0], bf[2 * jp + 1][1],
                       bs + (uint32_t)(((ks * 16 + b_krow) * BP2) + wn * 32 + jp * 8 + b_j4) * 4);
#pragma unroll
            for (int i = 0; i < 2; i++)
#pragma unroll
                for (int j = 0; j < 8; j++)
                    mma16(acc[i][j][0], acc[i][j][1], acc[i][j][2], acc[i][j][3],
                          af[i][0], af[i][1], af[i][2], af[i][3],
                          bf[j][0], bf[j][1]);
        }
    }

#pragma unroll
    for (int i = 0; i < 2; i++) {
#pragma unroll
        for (int j = 0; j < 8; j++) {
            const int n = n0 + wn * 64 + j * 8 + t * 2;
            const float2 bb = *(const float2*)&bias[n];
#pragma unroll
            for (int h2 = 0; h2 < 2; h2++) {
                const int m = m0 + wm * 32 + i * 16 + g + h2 * 8;
                float vx = acc[i][j][h2 * 2 + 0] + bb.x;
                float vy = acc[i][j][h2 * 2 + 1] + bb.y;
                if (MODE == 0) {
                    int bidx = m >> 10, tt = m & 1023;
                    int hh = n >> 6, d = n & 63;
                    __half2 hv = __floats2half2_rn(vx, vy);
                    *(__half2*)&((__half*)out)[(((size_t)(bidx * HH + hh) << 10) + tt) * DHX + d] = hv;
                } else {
                    *(float2*)&((float*)out)[(size_t)m * DD + n] = make_float2(vx, vy);
                }
            }
        }
    }
}

// ---------------------------------------------------------------------------
// Fused flash attention — R16 body: 128-row q-tile, 4 warps x 32 q-rows,
// 4-stage K/V cp.async ring (wait_group 2), bias L2 prefetch, __expf softmax.
// smem: Q 128x36w + 4 stages x [K 64x36w | V 64x36w] = 92160 B (2 CTAs).
// ---------------------------------------------------------------------------
#define QP2 36
#define QW  (128 * QP2)
#define KVW (64 * QP2)
#define NSTG 4
#define ASMEM ((QW + NSTG * 2 * KVW) * 4)   // 92160 bytes

__global__ __launch_bounds__(128)
void attn_h(const float* __restrict__ gb)
{
    extern __shared__ __align__(16) unsigned smw[];
    const uint32_t base = smem_u32(smw);
    unsigned* Q2 = smw;

    const int tid  = threadIdx.x;
    const int lane = tid & 31;
    const int warp = tid >> 5;
    const int g = lane >> 2;
    const int t = lane & 3;
    const int q0 = blockIdx.x * 128;
    const int h  = blockIdx.y;
    const int b  = blockIdx.z;
    const int qb = warp * 32;

    const __half* Qg = g_qh + (size_t)(b * HH + h) * TT * DHX;
    const __half* Kg = g_kh + (size_t)(b * HH + h) * TT * DHX;
    const __half* Vg = g_vh + (size_t)(b * HH + h) * TT * DHX;
    const float* gbrow = &gb[((size_t)b * TT + q0 + tid) * TT];

    const uint32_t sQ = base;
    auto sK = [&](int s) { return base + (uint32_t)(QW + s * 2 * KVW) * 4; };
    auto sV = [&](int s) { return base + (uint32_t)(QW + s * 2 * KVW + KVW) * 4; };

    const int a_row = (lane & 7) + ((lane >> 3) & 1) * 8;
    const int a_kw  = (lane >> 4) * 4;
    const int k_row = (lane & 7) + ((lane >> 4) & 1) * 8;
    const int k_kw  = ((lane >> 3) & 1) * 4;
    const int v_krow = (lane & 7) + ((lane >> 3) & 1) * 8;
    const int v_jw   = (lane >> 4) * 4;

    auto issue_kv = [&](int kt, int s) {
        const int k0 = kt * 64;
        const uint32_t kb = sK(s), vb = sV(s);
#pragma unroll
        for (int it = 0; it < 4; it++) {
            int idx = tid + it * 128;
            int r = idx >> 3, c = idx & 7;
            CP16(kb + (uint32_t)(r * QP2 + c * 4) * 4, &Kg[(size_t)(k0 + r) * DHX + c * 8]);
            CP16(vb + (uint32_t)(r * QP2 + c * 4) * 4, &Vg[(size_t)(k0 + r) * DHX + c * 8]);
        }
    };

#pragma unroll
    for (int it = 0; it < 8; it++) {
        int idx = tid + it * 128;
        int r = idx >> 3, u = idx & 7;
        uint4 qv = *(const uint4*)&Qg[(size_t)(q0 + r) * DHX + u * 8];
        *(uint4*)&Q2[r * QP2 + u * 4] = qv;
    }
    PREF_L2(gbrow);
    PREF_L2(gbrow + 32);
    issue_kv(0, 0); CP_COMMIT();
    issue_kv(1, 1); CP_COMMIT();
    issue_kv(2, 2); CP_COMMIT();
    __syncthreads();

    unsigned qf[2][4][4];
#pragma unroll
    for (int mt = 0; mt < 2; mt++)
#pragma unroll
        for (int ks = 0; ks < 4; ks++)
            ldsm4(qf[mt][ks][0], qf[mt][ks][1], qf[mt][ks][2], qf[mt][ks][3],
                  sQ + (uint32_t)(((qb + mt * 16 + a_row) * QP2) + ks * 8 + a_kw) * 4);

    float o[2][8][4];
#pragma unroll
    for (int mt = 0; mt < 2; mt++)
#pragma unroll
        for (int j = 0; j < 8; j++)
#pragma unroll
            for (int c = 0; c < 4; c++) o[mt][j][c] = 0.0f;
    float m_run[2][2] = {{-3e38f, -3e38f}, {-3e38f, -3e38f}};
    float l_run[2][2] = {{0.0f, 0.0f}, {0.0f, 0.0f}};

    for (int kt = 0; kt < 16; kt++) {
        const int k0 = kt * 64;
        CP_WAIT2();
        __syncthreads();
        if (kt + 3 < 16) issue_kv(kt + 3, (kt + 3) % NSTG);
        CP_COMMIT();

        if (kt + 1 < 16) {
            PREF_L2(gbrow + (kt + 1) * 64);
            PREF_L2(gbrow + (kt + 1) * 64 + 32);
        }

        const int s = kt % NSTG;
        const uint32_t kbs = sK(s), vbs = sV(s);

        // S = Q K^T
        float sc[2][8][4];
#pragma unroll
        for (int mt = 0; mt < 2; mt++)
#pragma unroll
            for (int j = 0; j < 8; j++)
#pragma unroll
                for (int c = 0; c < 4; c++) sc[mt][j][c] = 0.0f;

#pragma unroll
        for (int ks = 0; ks < 4; ks++) {
            unsigned kb[8][2];
#pragma unroll
            for (int jp = 0; jp < 4; jp++)
                ldsm4(kb[2 * jp][0], kb[2 * jp][1], kb[2 * jp + 1][0], kb[2 * jp + 1][1],
                      kbs + (uint32_t)(((jp * 16 + k_row) * QP2) + ks * 8 + k_kw) * 4);
#pragma unroll
            for (int mt = 0; mt < 2; mt++)
#pragma unroll
                for (int j = 0; j < 8; j++)
                    mma16(sc[mt][j][0], sc[mt][j][1], sc[mt][j][2], sc[mt][j][3],
                          qf[mt][ks][0], qf[mt][ks][1], qf[mt][ks][2], qf[mt][ks][3],
                          kb[j][0], kb[j][1]);
        }

        // scale + fused bias
#pragma unroll
        for (int mt = 0; mt < 2; mt++)
#pragma unroll
            for (int j = 0; j < 8; j++) {
                const int col = k0 + j * 8 + t * 2;
                const size_t i0 = ((size_t)b * TT + (q0 + qb + mt * 16 + g)) * TT + col;
                float2 b0 = *(const float2*)&gb[i0];
                float2 b1 = *(const float2*)&gb[i0 + (size_t)8 * TT];
                sc[mt][j][0] = sc[mt][j][0] * 0.125f + b0.x;
                sc[mt][j][1] = sc[mt][j][1] * 0.125f + b0.y;
                sc[mt][j][2] = sc[mt][j][2] * 0.125f + b1.x;
                sc[mt][j][3] = sc[mt][j][3] * 0.125f + b1.y;
            }

        // online softmax
#pragma unroll
        for (int mt = 0; mt < 2; mt++)
#pragma unroll
            for (int r = 0; r < 2; r++) {
                float mx = -3e38f;
#pragma unroll
                for (int j = 0; j < 8; j++)
                    mx = fmaxf(mx, fmaxf(sc[mt][j][2 * r], sc[mt][j][2 * r + 1]));
                mx = fmaxf(mx, __shfl_xor_sync(0xffffffffu, mx, 1));
                mx = fmaxf(mx, __shfl_xor_sync(0xffffffffu, mx, 2));
                float m_new = fmaxf(m_run[mt][r], mx);
                float alpha = __expf(m_run[mt][r] - m_new);
                m_run[mt][r] = m_new;
                float ls = 0.0f;
#pragma unroll
                for (int j = 0; j < 8; j++) {
                    float p0 = __expf(sc[mt][j][2 * r] - m_new);
                    float p1 = __expf(sc[mt][j][2 * r + 1] - m_new);
                    sc[mt][j][2 * r] = p0; sc[mt][j][2 * r + 1] = p1;
                    ls += p0 + p1;
                }
                ls += __shfl_xor_sync(0xffffffffu, ls, 1);
                ls += __shfl_xor_sync(0xffffffffu, ls, 2);
                l_run[mt][r] = l_run[mt][r] * alpha + ls;
#pragma unroll
                for (int j = 0; j < 8; j++) {
                    o[mt][j][2 * r] *= alpha;
                    o[mt][j][2 * r + 1] *= alpha;
                }
            }

        // pack P into A fragments in registers
        unsigned pf[2][4][4];
#pragma unroll
        for (int mt = 0; mt < 2; mt++)
#pragma unroll
            for (int c = 0; c < 4; c++) {
                pf[mt][c][0] = packh2(sc[mt][2 * c][0], sc[mt][2 * c][1]);
                pf[mt][c][1] = packh2(sc[mt][2 * c][2], sc[mt][2 * c][3]);
                pf[mt][c][2] = packh2(sc[mt][2 * c + 1][0], sc[mt][2 * c + 1][1]);
                pf[mt][c][3] = packh2(sc[mt][2 * c + 1][2], sc[mt][2 * c + 1][3]);
            }

        // O += P @ V
#pragma unroll
        for (int kv = 0; kv < 4; kv++) {
            unsigned vb[8][2];
#pragma unroll
            for (int jp = 0; jp < 4; jp++)
                ldsm4t(vb[2 * jp][0], vb[2 * jp][1], vb[2 * jp + 1][0], vb[2 * jp + 1][1],
                       vbs + (uint32_t)(((kv * 16 + v_krow) * QP2) + jp * 8 + v_jw) * 4);
#pragma unroll
            for (int mt = 0; mt < 2; mt++)
#pragma unroll
                for (int j = 0; j < 8; j++)
                    mma16(o[mt][j][0], o[mt][j][1], o[mt][j][2], o[mt][j][3],
                          pf[mt][kv][0], pf[mt][kv][1], pf[mt][kv][2], pf[mt][kv][3],
                          vb[j][0], vb[j][1]);
        }
    }

    // normalize + write fp16 (B,T,D)
#pragma unroll
    for (int mt = 0; mt < 2; mt++) {
        const float inv0 = 1.0f / l_run[mt][0];
        const float inv1 = 1.0f / l_run[mt][1];
#pragma unroll
        for (int j = 0; j < 8; j++) {
            const int d = h * DHX + j * 8 + t * 2;
            size_t r0 = ((size_t)b * TT + q0 + qb + mt * 16 + g) * DD + d;
            size_t r1 = r0 + (size_t)8 * DD;
            *(__half2*)&g_ctxh[r0] = __floats2half2_rn(o[mt][j][0] * inv0, o[mt][j][1] * inv0);
            *(__half2*)&g_ctxh[r1] = __floats2half2_rn(o[mt][j][2] * inv1, o[mt][j][3] * inv1);
        }
    }
}

// ---------------------------------------------------------------------------
// kernel_launch
// ---------------------------------------------------------------------------
extern "C" void kernel_launch(void* const* d_in, const int* in_sizes, int n_in,
                              void* d_out, int out_size)
{
    const float* query = (const float*)d_in[0];
    const float* key_  = (const float*)d_in[1];
    const float* value = (const float*)d_in[2];
    const float* sp    = (const float*)d_in[3];
    const float* edg   = (const float*)d_in[4];
    const unsigned int* mask = (const unsigned int*)d_in[5];
    const float* Wq = (const float*)d_in[6];
    const float* bq = (const float*)d_in[7];
    const float* Wk = (const float*)d_in[8];
    const float* bk = (const float*)d_in[9];
    const float* Wv = (const float*)d_in[10];
    const float* bv = (const float*)d_in[11];
    const float* Wo = (const float*)d_in[12];
    const float* bo = (const float*)d_in[13];
    float* out = (float*)d_out;

    __half *xq, *xk, *xv, *wq, *wk, *wv, *wo, *gq, *gk, *gv, *gctx;
    cudaGetSymbolAddress((void**)&xq, g_xq);
    cudaGetSymbolAddress((void**)&xk, g_xk);
    cudaGetSymbolAddress((void**)&xv, g_xv);
    cudaGetSymbolAddress((void**)&wq, g_wq);
    cudaGetSymbolAddress((void**)&wk, g_wk);
    cudaGetSymbolAddress((void**)&wv, g_wv);
    cudaGetSymbolAddress((void**)&wo, g_wo);
    cudaGetSymbolAddress((void**)&gq, g_qh);
    cudaGetSymbolAddress((void**)&gk, g_kh);
    cudaGetSymbolAddress((void**)&gv, g_vh);
    cudaGetSymbolAddress((void**)&gctx, g_ctxh);
    float* gb; cudaGetSymbolAddress((void**)&gb, g_bias);

    // all f32->fp16 conversions in ONE flattened launch (no empty blocks)
    to_half_flat<<<CONV_BLOCKS, 256>>>(
        (const float4*)query, (const float4*)key_, (const float4*)value,
        (const float4*)Wq, (const float4*)Wk, (const float4*)Wv, (const float4*)Wo,
        (uint2*)xq, (uint2*)xk, (uint2*)xv,
        (uint2*)wq, (uint2*)wk, (uint2*)wv, (uint2*)wo);

    cudaFuncSetAttribute(gemm_ha<0>, cudaFuncAttributeMaxDynamicSharedMemorySize, GSM);
    cudaFuncSetAttribute(gemm_ha<1>, cudaFuncAttributeMaxDynamicSharedMemorySize, GSM);
    cudaFuncSetAttribute(attn_h, cudaFuncAttributeMaxDynamicSharedMemorySize, ASMEM);

    // QKV projections (z=0..2) + bias fusion co-scheduled as z=3
    dim3 grid_qkv(DD / 128, MROWS / 128, 4);
    gemm_ha<0><<<grid_qkv, 256, GSM>>>(xq, xk, xv, wq, wk, wv,
                                       bq, bk, bv, gq, gk, gv,
                                       (const float4*)sp, (const float4*)edg, mask, (float4*)gb);

    dim3 attn_grid(TT / 128, HH, BB);   // (8, 16, 8)
    attn_h<<<attn_grid, 128, ASMEM>>>(gb);

    dim3 grid_o(DD / 128, MROWS / 128, 1);
    gemm_ha<1><<<grid_o, 256, GSM>>>(gctx, gctx, gctx, wo, wo, wo,
                                     bo, bo, bo, out, out, out,
                                     nullptr, nullptr, nullptr, nullptr);
}